// round 11
// baseline (speedup 1.0000x reference)
#include <cuda_runtime.h>
#include <cuda_fp16.h>
#include <cstdint>

#define SEQ   2048
#define BATCH 2
#define NTOK  (SEQ * BATCH)      // 4096
#define DIMM  2048
#define NH    32
#define NKV   8
#define HD    64
#define KVC   (2 * NKV * HD)     // 1024

// ---- scratch (static device globals: allocation-free) ----
__device__ __half g_xh[(size_t)NTOK * DIMM];
__device__ __half g_qh[(size_t)NTOK * DIMM];            // Q after rope (half)
__device__ __half g_kh[(size_t)NTOK * NKV * HD];        // K after rope (half)
__device__ __half g_vt[(size_t)BATCH * NKV * HD * SEQ]; // V^T [b][kvh][d][n]
__device__ __half g_ah[(size_t)NTOK * DIMM];            // attention out (half)
__device__ __half g_wqh[(size_t)DIMM * DIMM];           // Wq  [K][N] half
__device__ __half g_wkvh[(size_t)DIMM * KVC];           // Wkv [K][N] half
__device__ __half g_woh[(size_t)DIMM * DIMM];           // Wo  [K][N] half

__device__ __forceinline__ uint32_t smem_u32(const void* p) {
    uint32_t a;
    asm("{ .reg .u64 t; cvta.to.shared.u64 t, %1; cvt.u32.u64 %0, t; }" : "=r"(a) : "l"(p));
    return a;
}
__device__ __forceinline__ void mma_f16(float* d, const uint32_t* a, const uint32_t* b) {
    asm volatile(
        "mma.sync.aligned.m16n8k16.row.col.f32.f16.f16.f32 "
        "{%0,%1,%2,%3}, {%4,%5,%6,%7}, {%8,%9}, {%0,%1,%2,%3};"
        : "+f"(d[0]), "+f"(d[1]), "+f"(d[2]), "+f"(d[3])
        : "r"(a[0]), "r"(a[1]), "r"(a[2]), "r"(a[3]), "r"(b[0]), "r"(b[1]));
}
__device__ __forceinline__ void ldsm4(uint32_t* r, uint32_t addr) {
    asm volatile("ldmatrix.sync.aligned.m8n8.x4.shared.b16 {%0,%1,%2,%3}, [%4];"
        : "=r"(r[0]), "=r"(r[1]), "=r"(r[2]), "=r"(r[3]) : "r"(addr));
}
__device__ __forceinline__ void ldsm4t(uint32_t* r, uint32_t addr) {
    asm volatile("ldmatrix.sync.aligned.m8n8.x4.trans.shared.b16 {%0,%1,%2,%3}, [%4];"
        : "=r"(r[0]), "=r"(r[1]), "=r"(r[2]), "=r"(r[3]) : "r"(addr));
}
__device__ __forceinline__ void cp16(uint32_t dst, const void* src) {
    asm volatile("cp.async.cg.shared.global [%0], [%1], 16;" :: "r"(dst), "l"(src));
}
#define CP_COMMIT() asm volatile("cp.async.commit_group;" ::: "memory")

// ============================================================================
// One-shot fp32 -> fp16 convert of x, Wq, Wkv, Wo (8 elems / thread)
// ============================================================================
#define CN0 (NTOK * DIMM / 8)
#define CN1 (DIMM * DIMM / 8)
#define CN2 (DIMM * KVC / 8)
__global__ void conv_all(const float* __restrict__ x, const float* __restrict__ wq,
                         const float* __restrict__ wkv, const float* __restrict__ wo,
                         __half* __restrict__ xh, __half* __restrict__ wqh,
                         __half* __restrict__ wkvh, __half* __restrict__ woh)
{
    int i = blockIdx.x * blockDim.x + threadIdx.x;
    const float* src; __half* dst; int j = i;
    if (j < CN0) { src = x; dst = xh; }
    else {
        j -= CN0;
        if (j < CN1) { src = wq; dst = wqh; }
        else {
            j -= CN1;
            if (j < CN2) { src = wkv; dst = wkvh; }
            else { j -= CN2; if (j >= CN1) return; src = wo; dst = woh; }
        }
    }
    float4 a = ((const float4*)src)[2 * j];
    float4 b = ((const float4*)src)[2 * j + 1];
    half2 h0 = __floats2half2_rn(a.x, a.y), h1 = __floats2half2_rn(a.z, a.w);
    half2 h2 = __floats2half2_rn(b.x, b.y), h3 = __floats2half2_rn(b.z, b.w);
    uint4 r;
    r.x = *(uint32_t*)&h0; r.y = *(uint32_t*)&h1;
    r.z = *(uint32_t*)&h2; r.w = *(uint32_t*)&h3;
    ((uint4*)dst)[j] = r;
}

// ============================================================================
// fp16 mma.sync GEMM: 256 threads (8 warps, 2M x 4N), warp tile 64x32.
// CTA 128x128, BK=64, 3-stage cp.async, B = W[K][N] via ldmatrix.trans.
// ~64 acc regs/thread -> no spills, 2 CTAs/SM (smem-limited) = 16 warps/SM.
// mode 0: fp32 out (O-proj).  mode 1: blocks 0-15 Q (rope), 16-23 KV (K/V).
// smem: A 3x18432 @0, B 3x17408 @55296 -> 107520 B.
// ============================================================================
#define G_SMEM 107520

__global__ __launch_bounds__(256) void gemm_h(
    const __half* __restrict__ A,
    const __half* __restrict__ W0, const __half* __restrict__ W1,
    float* __restrict__ Cf, __half* __restrict__ qh,
    __half* __restrict__ kh, __half* __restrict__ vt,
    const float* __restrict__ cb, const float* __restrict__ sb,
    int M, int K, int mode)
{
    extern __shared__ __half hsm[];
    const uint32_t sbase = smem_u32(hsm);
    const int tid = threadIdx.x;
    const int wid = tid >> 5, lane = tid & 31;
    const int g = lane >> 2, tg = lane & 3;
    const int wm = wid & 1, wn = wid >> 1;        // 2 M-blocks x 4 N-blocks
    const int nb = blockIdx.x;
    const int m0 = blockIdx.y * 128;

    const __half* W; int Nw, ncol0;
    if (mode == 0 || nb < 16) { W = W0; Nw = DIMM; ncol0 = nb * 128; }
    else                      { W = W1; Nw = KVC;  ncol0 = (nb - 16) * 128; }

    const int arow  = (lane & 7) + ((lane >> 3) & 1) * 8;
    const int akoff = (lane >> 4) * 8;
    const int trow = (lane & 7) + ((lane >> 3) & 1) * 8;
    const int tcol = ((lane >> 4) & 1) * 8;

    const __half* Ab = A + (size_t)m0 * K;

    float acc[4][4][4];
    #pragma unroll
    for (int mt = 0; mt < 4; ++mt)
        #pragma unroll
        for (int nt = 0; nt < 4; ++nt)
            #pragma unroll
            for (int v = 0; v < 4; ++v) acc[mt][nt][v] = 0.f;

    const int NC = K / 64;     // 32

    auto issue_chunk = [&](int s, int k0) {
        const uint32_t abase = sbase + (uint32_t)s * 18432u;
        const uint32_t bbase = sbase + 55296u + (uint32_t)s * 17408u;
        #pragma unroll
        for (int i = 0; i < 4; ++i) {
            const int idx = tid + 256 * i;
            {   // A: [128 m][64 k], pitch 144 B
                const int row = idx >> 3, seg = idx & 7;
                cp16(abase + (uint32_t)(row * 144 + seg * 16),
                     Ab + (size_t)row * K + k0 + seg * 8);
            }
            {   // B: [64 k][128 n], pitch 272 B
                const int row = idx >> 4, seg = idx & 15;
                cp16(bbase + (uint32_t)(row * 272 + seg * 16),
                     W + (size_t)(k0 + row) * Nw + ncol0 + seg * 8);
            }
        }
        CP_COMMIT();
    };

    issue_chunk(0, 0);
    issue_chunk(1, 64);

    for (int c = 0; c < NC; ++c) {
        const int s = c % 3;
        if (c + 2 < NC) {
            issue_chunk((c + 2) % 3, (c + 2) * 64);
            asm volatile("cp.async.wait_group 2;" ::: "memory");
        } else if (c + 1 < NC) {
            asm volatile("cp.async.wait_group 1;" ::: "memory");
        } else {
            asm volatile("cp.async.wait_group 0;" ::: "memory");
        }
        __syncthreads();

        const uint32_t As = sbase + (uint32_t)s * 18432u;
        const uint32_t Bs = sbase + 55296u + (uint32_t)s * 17408u;
        #pragma unroll
        for (int ks = 0; ks < 4; ++ks) {
            uint32_t af[4][4];
            #pragma unroll
            for (int mt = 0; mt < 4; ++mt)
                ldsm4(af[mt], As + (uint32_t)((wm * 64 + mt * 16 + arow) * 72 + ks * 16 + akoff) * 2u);
            #pragma unroll
            for (int ntp = 0; ntp < 2; ++ntp) {
                uint32_t t4[4];
                ldsm4t(t4, Bs + (uint32_t)((ks * 16 + trow) * 136 + wn * 32 + ntp * 16 + tcol) * 2u);
                #pragma unroll
                for (int mt = 0; mt < 4; ++mt) {
                    mma_f16(acc[mt][2 * ntp],     af[mt], t4);
                    mma_f16(acc[mt][2 * ntp + 1], af[mt], t4 + 2);
                }
            }
        }
        __syncthreads();
    }

    // ---- epilogues ----
    if (mode == 0) {
        #pragma unroll
        for (int mt = 0; mt < 4; ++mt) {
            const int row = m0 + wm * 64 + mt * 16 + g;
            #pragma unroll
            for (int nt = 0; nt < 4; ++nt) {
                const int col = ncol0 + wn * 32 + nt * 8 + 2 * tg;
                *(float2*)(Cf + (size_t)row * DIMM + col) =
                    make_float2(acc[mt][nt][0], acc[mt][nt][1]);
                *(float2*)(Cf + (size_t)(row + 8) * DIMM + col) =
                    make_float2(acc[mt][nt][2], acc[mt][nt][3]);
            }
        }
    } else if (nb < 16) {   // Q: rope -> qh
        #pragma unroll
        for (int mt = 0; mt < 4; ++mt) {
            const int row = m0 + wm * 64 + mt * 16 + g;
            const int n1 = row & (SEQ - 1), n2 = (row + 8) & (SEQ - 1);
            #pragma unroll
            for (int nt = 0; nt < 4; ++nt) {
                const int col = ncol0 + wn * 32 + nt * 8 + 2 * tg;
                const int fi = (col & 63) >> 1;
                float c1 = cb[n1 * 32 + fi], s1 = sb[n1 * 32 + fi];
                float c2 = cb[n2 * 32 + fi], s2 = sb[n2 * 32 + fi];
                *(half2*)(qh + (size_t)row * DIMM + col) = __floats2half2_rn(
                    acc[mt][nt][0] * c1 - acc[mt][nt][1] * s1,
                    acc[mt][nt][0] * s1 + acc[mt][nt][1] * c1);
                *(half2*)(qh + (size_t)(row + 8) * DIMM + col) = __floats2half2_rn(
                    acc[mt][nt][2] * c2 - acc[mt][nt][3] * s2,
                    acc[mt][nt][2] * s2 + acc[mt][nt][3] * c2);
            }
        }
    } else {                // KV: K rope -> kh, V transposed scatter -> vt
        #pragma unroll
        for (int mt = 0; mt < 4; ++mt) {
            const int row = m0 + wm * 64 + mt * 16 + g;
            const int n1 = row & (SEQ - 1), n2 = (row + 8) & (SEQ - 1);
            const int b_ = row >> 11;
            #pragma unroll
            for (int nt = 0; nt < 4; ++nt) {
                const int col = ncol0 + wn * 32 + nt * 8 + 2 * tg;
                if (col < 512) {
                    const int fi = (col & 63) >> 1;
                    float c1 = cb[n1 * 32 + fi], s1 = sb[n1 * 32 + fi];
                    float c2 = cb[n2 * 32 + fi], s2 = sb[n2 * 32 + fi];
                    *(half2*)(kh + (size_t)row * 512 + col) = __floats2half2_rn(
                        acc[mt][nt][0] * c1 - acc[mt][nt][1] * s1,
                        acc[mt][nt][0] * s1 + acc[mt][nt][1] * c1);
                    *(half2*)(kh + (size_t)(row + 8) * 512 + col) = __floats2half2_rn(
                        acc[mt][nt][2] * c2 - acc[mt][nt][3] * s2,
                        acc[mt][nt][2] * s2 + acc[mt][nt][3] * c2);
                } else {
                    const int cm = col - 512;
                    const int kvh = cm >> 6, d = cm & 63;
                    __half* vb = vt + ((size_t)((b_ * NKV + kvh) * HD + d)) * SEQ;
                    vb[n1]       = __float2half_rn(acc[mt][nt][0]);
                    vb[SEQ + n1] = __float2half_rn(acc[mt][nt][1]);
                    vb[n2]       = __float2half_rn(acc[mt][nt][2]);
                    vb[SEQ + n2] = __float2half_rn(acc[mt][nt][3]);
                }
            }
        }
    }
}

// ============================================================================
// fp16 flash attention (R8 version: 128-wide key tiles, register prefetch)
// smem halves: Ps[128][136]@0, Ks[128][72]@17408, Vs[64][136]@26624 (70656 B)
// ============================================================================
#define FH_SMEM 70656
#define QTB     (SEQ / 128)                     // 16

__global__ __launch_bounds__(256) void flash_h(
    const __half* __restrict__ qh, const __half* __restrict__ kh,
    const __half* __restrict__ vt, __half* __restrict__ oh)
{
    extern __shared__ __half fsh[];
    __half* Ps = fsh;                    // [128][136] (Q staging, then P)
    __half* Ks = fsh + 128 * 136;        // [128][72]  rows = keys
    __half* Vs = Ks + 128 * 72;          // [64][136]  rows = dims (V^T)
    const uint32_t Pu = smem_u32(Ps);
    const uint32_t Ku = smem_u32(Ks);
    const uint32_t Vu = smem_u32(Vs);

    const int qtb = (QTB - 1) - blockIdx.x;   // big tiles first
    const int h = blockIdx.y, b = blockIdx.z;
    const int kvh = h & (NKV - 1);
    const int bk = b * NKV + kvh;
    const int tid = threadIdx.x;
    const int wid = tid >> 5, lane = tid & 31;
    const int g = lane >> 2, tg = lane & 3;
    const int wrow = wid * 16;
    const int q0 = qtb * 128;

    const int arow  = (lane & 7) + ((lane >> 3) & 1) * 8;
    const int akoff = (lane >> 4) * 8;
    const int brow  = (lane & 7) + ((lane >> 4) & 1) * 8;
    const int bkoff = ((lane >> 3) & 1) * 8;

    // ---- stage Q (pitch 136) ----
    #pragma unroll
    for (int i = 0; i < 4; ++i) {
        int idx = tid + i * 256;
        int row = idx >> 3, seg = idx & 7;
        *(uint4*)&Ps[row * 136 + seg * 8] =
            *(const uint4*)&qh[(size_t)(b * SEQ + q0 + row) * DIMM + h * HD + seg * 8];
    }
    __syncthreads();

    uint32_t qf[4][4];
    #pragma unroll
    for (int ks = 0; ks < 4; ++ks)
        ldsm4(qf[ks], Pu + (uint32_t)((wrow + arow) * 136 + ks * 16 + akoff) * 2u);

    float m_g = -1e30f, m_g8 = -1e30f, l_g = 0.f, l_g8 = 0.f;
    float acc[8][4];
    #pragma unroll
    for (int nt = 0; nt < 8; ++nt)
        #pragma unroll
        for (int v = 0; v < 4; ++v) acc[nt][v] = 0.f;

    // prologue: prefetch tile 0 (K: 128x64, V: 64x128)
    uint4 kr[4], vr[4];
    #pragma unroll
    for (int i = 0; i < 4; ++i) {
        int idx = tid + i * 256;
        { int r = idx >> 3, seg = idx & 7;
          kr[i] = *(const uint4*)&kh[(size_t)(b * SEQ + r) * 512 + kvh * HD + seg * 8]; }
        { int r = idx >> 4, seg = idx & 15;
          vr[i] = *(const uint4*)&vt[((size_t)bk * HD + r) * SEQ + seg * 8]; }
    }

    for (int kt = 0; kt <= qtb; ++kt) {
        __syncthreads();
        #pragma unroll
        for (int i = 0; i < 4; ++i) {
            int idx = tid + i * 256;
            { int r = idx >> 3, seg = idx & 7;
              *(uint4*)&Ks[r * 72 + seg * 8] = kr[i]; }
            { int r = idx >> 4, seg = idx & 15;
              *(uint4*)&Vs[r * 136 + seg * 8] = vr[i]; }
        }
        __syncthreads();

        if (kt < qtb) {
            #pragma unroll
            for (int i = 0; i < 4; ++i) {
                int idx = tid + i * 256;
                { int r = idx >> 3, seg = idx & 7;
                  kr[i] = *(const uint4*)&kh[(size_t)(b * SEQ + (kt + 1) * 128 + r) * 512 + kvh * HD + seg * 8]; }
                { int r = idx >> 4, seg = idx & 15;
                  vr[i] = *(const uint4*)&vt[((size_t)bk * HD + r) * SEQ + (kt + 1) * 128 + seg * 8]; }
            }
        }

        // ---- S = Q @ K^T  (128 keys) ----
        float sA[16][4];
        #pragma unroll
        for (int nt = 0; nt < 16; ++nt)
            #pragma unroll
            for (int v = 0; v < 4; ++v) sA[nt][v] = 0.f;
        #pragma unroll
        for (int ks = 0; ks < 4; ++ks) {
            #pragma unroll
            for (int ntp = 0; ntp < 8; ++ntp) {
                uint32_t t4[4];
                ldsm4(t4, Ku + (uint32_t)((ntp * 16 + brow) * 72 + ks * 16 + bkoff) * 2u);
                mma_f16(sA[2 * ntp],     qf[ks], t4);
                mma_f16(sA[2 * ntp + 1], qf[ks], t4 + 2);
            }
        }
        #pragma unroll
        for (int nt = 0; nt < 16; ++nt) {
            sA[nt][0] *= 0.125f; sA[nt][1] *= 0.125f;
            sA[nt][2] *= 0.125f; sA[nt][3] *= 0.125f;
        }

        // ---- causal mask (diagonal tile only) ----
        if (kt == qtb) {
            const int r1 = wrow + g, r2 = wrow + g + 8;
            #pragma unroll
            for (int nt = 0; nt < 16; ++nt) {
                const int col = nt * 8 + 2 * tg;
                if (col > r1)     sA[nt][0] = -1e30f;
                if (col + 1 > r1) sA[nt][1] = -1e30f;
                if (col > r2)     sA[nt][2] = -1e30f;
                if (col + 1 > r2) sA[nt][3] = -1e30f;
            }
        }

        // ---- online softmax ----
        float mxg = -1e30f, mxg8 = -1e30f;
        #pragma unroll
        for (int nt = 0; nt < 16; ++nt) {
            mxg  = fmaxf(mxg,  fmaxf(sA[nt][0], sA[nt][1]));
            mxg8 = fmaxf(mxg8, fmaxf(sA[nt][2], sA[nt][3]));
        }
        mxg  = fmaxf(mxg,  __shfl_xor_sync(0xffffffffu, mxg, 1));
        mxg  = fmaxf(mxg,  __shfl_xor_sync(0xffffffffu, mxg, 2));
        mxg8 = fmaxf(mxg8, __shfl_xor_sync(0xffffffffu, mxg8, 1));
        mxg8 = fmaxf(mxg8, __shfl_xor_sync(0xffffffffu, mxg8, 2));

        const float mn_g  = fmaxf(m_g,  mxg);
        const float mn_g8 = fmaxf(m_g8, mxg8);
        const float cr_g  = __expf(m_g  - mn_g);
        const float cr_g8 = __expf(m_g8 - mn_g8);

        float sum_g = 0.f, sum_g8 = 0.f;
        #pragma unroll
        for (int nt = 0; nt < 16; ++nt) {
            sA[nt][0] = __expf(sA[nt][0] - mn_g);
            sA[nt][1] = __expf(sA[nt][1] - mn_g);
            sA[nt][2] = __expf(sA[nt][2] - mn_g8);
            sA[nt][3] = __expf(sA[nt][3] - mn_g8);
            sum_g  += sA[nt][0] + sA[nt][1];
            sum_g8 += sA[nt][2] + sA[nt][3];
        }
        sum_g  += __shfl_xor_sync(0xffffffffu, sum_g, 1);
        sum_g  += __shfl_xor_sync(0xffffffffu, sum_g, 2);
        sum_g8 += __shfl_xor_sync(0xffffffffu, sum_g8, 1);
        sum_g8 += __shfl_xor_sync(0xffffffffu, sum_g8, 2);

        m_g = mn_g;  l_g  = l_g  * cr_g  + sum_g;
        m_g8 = mn_g8; l_g8 = l_g8 * cr_g8 + sum_g8;

        // ---- P -> smem (per-warp-private rows, pitch 136) ----
        {
            __half* pr = Ps + (wrow + g) * 136;
            #pragma unroll
            for (int nt = 0; nt < 16; ++nt) {
                *(half2*)(pr + nt * 8 + 2 * tg) = __floats2half2_rn(sA[nt][0], sA[nt][1]);
                *(half2*)(pr + 8 * 136 + nt * 8 + 2 * tg) = __floats2half2_rn(sA[nt][2], sA[nt][3]);
            }
        }
        __syncwarp();

        #pragma unroll
        for (int nt = 0; nt < 8; ++nt) {
            acc[nt][0] *= cr_g;  acc[nt][1] *= cr_g;
            acc[nt][2] *= cr_g8; acc[nt][3] *= cr_g8;
        }

        // ---- O += P @ V  (k = 128 keys -> 8 ks steps) ----
        #pragma unroll
        for (int ks = 0; ks < 8; ++ks) {
            uint32_t af[4];
            ldsm4(af, Pu + (uint32_t)((wrow + arow) * 136 + ks * 16 + akoff) * 2u);
            #pragma unroll
            for (int ntp = 0; ntp < 4; ++ntp) {
                uint32_t t4[4];
                ldsm4(t4, Vu + (uint32_t)((ntp * 16 + brow) * 136 + ks * 16 + bkoff) * 2u);
                mma_f16(acc[2 * ntp],     af, t4);
                mma_f16(acc[2 * ntp + 1], af, t4 + 2);
            }
        }
    }

    // ---- epilogue ----
    const float il_g = 1.f / l_g, il_g8 = 1.f / l_g8;
    __half* ob  = oh + (size_t)(b * SEQ + q0 + wrow + g) * DIMM + h * HD;
    __half* ob8 = ob + 8 * DIMM;
    #pragma unroll
    for (int nt = 0; nt < 8; ++nt) {
        const int col = nt * 8 + 2 * tg;
        *(half2*)(ob + col)  = __floats2half2_rn(acc[nt][0] * il_g,  acc[nt][1] * il_g);
        *(half2*)(ob8 + col) = __floats2half2_rn(acc[nt][2] * il_g8, acc[nt][3] * il_g8);
    }
}

// ============================================================================
extern "C" void kernel_launch(void* const* d_in, const int* in_sizes, int n_in,
                              void* d_out, int out_size)
{
    const float* x   = (const float*)d_in[0];
    const float* Wq  = (const float*)d_in[1];
    const float* Wkv = (const float*)d_in[2];
    const float* Wo  = (const float*)d_in[3];
    const float* cb  = (const float*)d_in[4];
    const float* sb  = (const float*)d_in[5];
    float* out = (float*)d_out;

    __half *xh, *qhp, *khp, *vtp, *ahp, *wqh, *wkvh, *woh;
    cudaGetSymbolAddress((void**)&xh,   g_xh);
    cudaGetSymbolAddress((void**)&qhp,  g_qh);
    cudaGetSymbolAddress((void**)&khp,  g_kh);
    cudaGetSymbolAddress((void**)&vtp,  g_vt);
    cudaGetSymbolAddress((void**)&ahp,  g_ah);
    cudaGetSymbolAddress((void**)&wqh,  g_wqh);
    cudaGetSymbolAddress((void**)&wkvh, g_wkvh);
    cudaGetSymbolAddress((void**)&woh,  g_woh);

    cudaFuncSetAttribute(gemm_h,
                         cudaFuncAttributeMaxDynamicSharedMemorySize, G_SMEM);
    cudaFuncSetAttribute(flash_h,
                         cudaFuncAttributeMaxDynamicSharedMemorySize, FH_SMEM);

    // one-shot fp16 conversion of x + all weights
    {
        int total = CN0 + 2 * CN1 + CN2;
        conv_all<<<(total + 255) / 256, 256>>>(x, Wq, Wkv, Wo, xh, wqh, wkvh, woh);
    }

    // combined Q+KV projection (fused rope / V-transpose epilogues)
    gemm_h<<<dim3(24, NTOK / 128), 256, G_SMEM>>>(
        xh, wqh, wkvh, nullptr, qhp, khp, vtp, cb, sb, NTOK, DIMM, 1);

    // fp16 tensor-core causal GQA flash attention
    flash_h<<<dim3(QTB, NH, BATCH), 256, FH_SMEM>>>(qhp, khp, vtp, ahp);

    // out = att @ Wo (fp32 out)
    gemm_h<<<dim3(16, NTOK / 128), 256, G_SMEM>>>(
        ahp, woh, nullptr, out, nullptr, nullptr, nullptr, nullptr, nullptr,
        NTOK, DIMM, 0);
}

// round 12
// speedup vs baseline: 1.0705x; 1.0705x over previous
#include <cuda_runtime.h>
#include <cuda_fp16.h>
#include <cstdint>

#define SEQ   2048
#define BATCH 2
#define NTOK  (SEQ * BATCH)      // 4096
#define DIMM  2048
#define NH    32
#define NKV   8
#define HD    64
#define KVC   (2 * NKV * HD)     // 1024

// ---- scratch (static device globals: allocation-free) ----
__device__ __half g_xh[(size_t)NTOK * DIMM];
__device__ __half g_qh[(size_t)NTOK * DIMM];            // Q after rope (half)
__device__ __half g_kh[(size_t)NTOK * NKV * HD];        // K after rope (half)
__device__ __half g_vt[(size_t)BATCH * NKV * HD * SEQ]; // V^T [b][kvh][d][n]
__device__ __half g_ah[(size_t)NTOK * DIMM];            // attention out (half)
__device__ __half g_wqh[(size_t)DIMM * DIMM];           // Wq  [K][N] half
__device__ __half g_wkvh[(size_t)DIMM * KVC];           // Wkv [K][N] half
__device__ __half g_woh[(size_t)DIMM * DIMM];           // Wo  [K][N] half

__device__ __forceinline__ uint32_t smem_u32(const void* p) {
    uint32_t a;
    asm("{ .reg .u64 t; cvta.to.shared.u64 t, %1; cvt.u32.u64 %0, t; }" : "=r"(a) : "l"(p));
    return a;
}
__device__ __forceinline__ void mma_f16(float* d, const uint32_t* a, const uint32_t* b) {
    asm volatile(
        "mma.sync.aligned.m16n8k16.row.col.f32.f16.f16.f32 "
        "{%0,%1,%2,%3}, {%4,%5,%6,%7}, {%8,%9}, {%0,%1,%2,%3};"
        : "+f"(d[0]), "+f"(d[1]), "+f"(d[2]), "+f"(d[3])
        : "r"(a[0]), "r"(a[1]), "r"(a[2]), "r"(a[3]), "r"(b[0]), "r"(b[1]));
}
__device__ __forceinline__ void ldsm4(uint32_t* r, uint32_t addr) {
    asm volatile("ldmatrix.sync.aligned.m8n8.x4.shared.b16 {%0,%1,%2,%3}, [%4];"
        : "=r"(r[0]), "=r"(r[1]), "=r"(r[2]), "=r"(r[3]) : "r"(addr));
}
__device__ __forceinline__ void ldsm4t(uint32_t* r, uint32_t addr) {
    asm volatile("ldmatrix.sync.aligned.m8n8.x4.trans.shared.b16 {%0,%1,%2,%3}, [%4];"
        : "=r"(r[0]), "=r"(r[1]), "=r"(r[2]), "=r"(r[3]) : "r"(addr));
}
__device__ __forceinline__ void cp16(uint32_t dst, const void* src) {
    asm volatile("cp.async.cg.shared.global [%0], [%1], 16;" :: "r"(dst), "l"(src));
}
#define CP_COMMIT() asm volatile("cp.async.commit_group;" ::: "memory")

// ============================================================================
// One-shot fp32 -> fp16 convert of x, Wq, Wkv, Wo (8 elems / thread)
// ============================================================================
#define CN0 (NTOK * DIMM / 8)
#define CN1 (DIMM * DIMM / 8)
#define CN2 (DIMM * KVC / 8)
__global__ void conv_all(const float* __restrict__ x, const float* __restrict__ wq,
                         const float* __restrict__ wkv, const float* __restrict__ wo,
                         __half* __restrict__ xh, __half* __restrict__ wqh,
                         __half* __restrict__ wkvh, __half* __restrict__ woh)
{
    int i = blockIdx.x * blockDim.x + threadIdx.x;
    const float* src; __half* dst; int j = i;
    if (j < CN0) { src = x; dst = xh; }
    else {
        j -= CN0;
        if (j < CN1) { src = wq; dst = wqh; }
        else {
            j -= CN1;
            if (j < CN2) { src = wkv; dst = wkvh; }
            else { j -= CN2; if (j >= CN1) return; src = wo; dst = woh; }
        }
    }
    float4 a = ((const float4*)src)[2 * j];
    float4 b = ((const float4*)src)[2 * j + 1];
    half2 h0 = __floats2half2_rn(a.x, a.y), h1 = __floats2half2_rn(a.z, a.w);
    half2 h2 = __floats2half2_rn(b.x, b.y), h3 = __floats2half2_rn(b.z, b.w);
    uint4 r;
    r.x = *(uint32_t*)&h0; r.y = *(uint32_t*)&h1;
    r.z = *(uint32_t*)&h2; r.w = *(uint32_t*)&h3;
    ((uint4*)dst)[j] = r;
}

// ============================================================================
// fp16 mma.sync GEMM (R9 config — measured best O-proj 117us @ 48% tensor):
// 128 threads (4 warps, 2M x 2N), warp tile 64x64, BK=64, 3-stage cp.async,
// B = W[K][N] via ldmatrix.trans, natural register allocation (no bound).
// mode 0: fp32 out (O-proj).  mode 1: blocks 0-15 Q (rope), 16-23 KV (K/V).
// smem bytes: A 3x18432 @0, B 3x17408 @55296 -> 107520 total.
// ============================================================================
#define G_SMEM 107520

__global__ __launch_bounds__(128) void gemm_h(
    const __half* __restrict__ A,
    const __half* __restrict__ W0, const __half* __restrict__ W1,
    float* __restrict__ Cf, __half* __restrict__ qh,
    __half* __restrict__ kh, __half* __restrict__ vt,
    const float* __restrict__ cb, const float* __restrict__ sb,
    int M, int K, int mode)
{
    extern __shared__ __half hsm[];
    const uint32_t sbase = smem_u32(hsm);
    const int tid = threadIdx.x;
    const int wid = tid >> 5, lane = tid & 31;
    const int g = lane >> 2, tg = lane & 3;
    const int wm = wid & 1, wn = wid >> 1;
    const int nb = blockIdx.x;
    const int m0 = blockIdx.y * 128;

    const __half* W; int Nw, ncol0;
    if (mode == 0 || nb < 16) { W = W0; Nw = DIMM; ncol0 = nb * 128; }
    else                      { W = W1; Nw = KVC;  ncol0 = (nb - 16) * 128; }

    const int arow  = (lane & 7) + ((lane >> 3) & 1) * 8;
    const int akoff = (lane >> 4) * 8;
    const int trow = (lane & 7) + ((lane >> 3) & 1) * 8;
    const int tcol = ((lane >> 4) & 1) * 8;

    const __half* Ab = A + (size_t)m0 * K;

    float acc[4][8][4];
    #pragma unroll
    for (int mt = 0; mt < 4; ++mt)
        #pragma unroll
        for (int nt = 0; nt < 8; ++nt)
            #pragma unroll
            for (int v = 0; v < 4; ++v) acc[mt][nt][v] = 0.f;

    const int NC = K / 64;     // 32

    auto issue_chunk = [&](int s, int k0) {
        const uint32_t abase = sbase + (uint32_t)s * 18432u;
        const uint32_t bbase = sbase + 55296u + (uint32_t)s * 17408u;
        #pragma unroll
        for (int i = 0; i < 8; ++i) {
            const int idx = tid + 128 * i;
            {   // A: [128 m][64 k], pitch 144 B
                const int row = idx >> 3, seg = idx & 7;
                cp16(abase + (uint32_t)(row * 144 + seg * 16),
                     Ab + (size_t)row * K + k0 + seg * 8);
            }
            {   // B: [64 k][128 n], pitch 272 B
                const int row = idx >> 4, seg = idx & 15;
                cp16(bbase + (uint32_t)(row * 272 + seg * 16),
                     W + (size_t)(k0 + row) * Nw + ncol0 + seg * 8);
            }
        }
        CP_COMMIT();
    };

    issue_chunk(0, 0);
    issue_chunk(1, 64);

    for (int c = 0; c < NC; ++c) {
        const int s = c % 3;
        if (c + 2 < NC) {
            issue_chunk((c + 2) % 3, (c + 2) * 64);
            asm volatile("cp.async.wait_group 2;" ::: "memory");
        } else if (c + 1 < NC) {
            asm volatile("cp.async.wait_group 1;" ::: "memory");
        } else {
            asm volatile("cp.async.wait_group 0;" ::: "memory");
        }
        __syncthreads();

        const uint32_t As = sbase + (uint32_t)s * 18432u;
        const uint32_t Bs = sbase + 55296u + (uint32_t)s * 17408u;
        #pragma unroll
        for (int ks = 0; ks < 4; ++ks) {
            uint32_t af[4][4];
            #pragma unroll
            for (int mt = 0; mt < 4; ++mt)
                ldsm4(af[mt], As + (uint32_t)((wm * 64 + mt * 16 + arow) * 72 + ks * 16 + akoff) * 2u);
            #pragma unroll
            for (int ntp = 0; ntp < 4; ++ntp) {
                uint32_t t4[4];
                ldsm4t(t4, Bs + (uint32_t)((ks * 16 + trow) * 136 + wn * 64 + ntp * 16 + tcol) * 2u);
                #pragma unroll
                for (int mt = 0; mt < 4; ++mt) {
                    mma_f16(acc[mt][2 * ntp],     af[mt], t4);
                    mma_f16(acc[mt][2 * ntp + 1], af[mt], t4 + 2);
                }
            }
        }
        __syncthreads();
    }

    // ---- epilogues ----
    if (mode == 0) {
        #pragma unroll
        for (int mt = 0; mt < 4; ++mt) {
            const int row = m0 + wm * 64 + mt * 16 + g;
            #pragma unroll
            for (int nt = 0; nt < 8; ++nt) {
                const int col = ncol0 + wn * 64 + nt * 8 + 2 * tg;
                *(float2*)(Cf + (size_t)row * DIMM + col) =
                    make_float2(acc[mt][nt][0], acc[mt][nt][1]);
                *(float2*)(Cf + (size_t)(row + 8) * DIMM + col) =
                    make_float2(acc[mt][nt][2], acc[mt][nt][3]);
            }
        }
    } else if (nb < 16) {   // Q: rope -> qh
        #pragma unroll
        for (int mt = 0; mt < 4; ++mt) {
            const int row = m0 + wm * 64 + mt * 16 + g;
            const int n1 = row & (SEQ - 1), n2 = (row + 8) & (SEQ - 1);
            #pragma unroll
            for (int nt = 0; nt < 8; ++nt) {
                const int col = ncol0 + wn * 64 + nt * 8 + 2 * tg;
                const int fi = (col & 63) >> 1;
                float c1 = cb[n1 * 32 + fi], s1 = sb[n1 * 32 + fi];
                float c2 = cb[n2 * 32 + fi], s2 = sb[n2 * 32 + fi];
                *(half2*)(qh + (size_t)row * DIMM + col) = __floats2half2_rn(
                    acc[mt][nt][0] * c1 - acc[mt][nt][1] * s1,
                    acc[mt][nt][0] * s1 + acc[mt][nt][1] * c1);
                *(half2*)(qh + (size_t)(row + 8) * DIMM + col) = __floats2half2_rn(
                    acc[mt][nt][2] * c2 - acc[mt][nt][3] * s2,
                    acc[mt][nt][2] * s2 + acc[mt][nt][3] * c2);
            }
        }
    } else {                // KV: K rope -> kh, V transposed scatter -> vt
        #pragma unroll
        for (int mt = 0; mt < 4; ++mt) {
            const int row = m0 + wm * 64 + mt * 16 + g;
            const int n1 = row & (SEQ - 1), n2 = (row + 8) & (SEQ - 1);
            const int b_ = row >> 11;
            #pragma unroll
            for (int nt = 0; nt < 8; ++nt) {
                const int col = ncol0 + wn * 64 + nt * 8 + 2 * tg;
                if (col < 512) {
                    const int fi = (col & 63) >> 1;
                    float c1 = cb[n1 * 32 + fi], s1 = sb[n1 * 32 + fi];
                    float c2 = cb[n2 * 32 + fi], s2 = sb[n2 * 32 + fi];
                    *(half2*)(kh + (size_t)row * 512 + col) = __floats2half2_rn(
                        acc[mt][nt][0] * c1 - acc[mt][nt][1] * s1,
                        acc[mt][nt][0] * s1 + acc[mt][nt][1] * c1);
                    *(half2*)(kh + (size_t)(row + 8) * 512 + col) = __floats2half2_rn(
                        acc[mt][nt][2] * c2 - acc[mt][nt][3] * s2,
                        acc[mt][nt][2] * s2 + acc[mt][nt][3] * c2);
                } else {
                    const int cm = col - 512;
                    const int kvh = cm >> 6, d = cm & 63;
                    __half* vb = vt + ((size_t)((b_ * NKV + kvh) * HD + d)) * SEQ;
                    vb[n1]       = __float2half_rn(acc[mt][nt][0]);
                    vb[SEQ + n1] = __float2half_rn(acc[mt][nt][1]);
                    vb[n2]       = __float2half_rn(acc[mt][nt][2]);
                    vb[SEQ + n2] = __float2half_rn(acc[mt][nt][3]);
                }
            }
        }
    }
}

// ============================================================================
// fp16 flash attention (R8 version — measured in best 490us total):
// 128-wide key tiles, register prefetch.
// smem halves: Ps[128][136]@0, Ks[128][72]@17408, Vs[64][136]@26624 (70656 B)
// ============================================================================
#define FH_SMEM 70656
#define QTB     (SEQ / 128)                     // 16

__global__ __launch_bounds__(256) void flash_h(
    const __half* __restrict__ qh, const __half* __restrict__ kh,
    const __half* __restrict__ vt, __half* __restrict__ oh)
{
    extern __shared__ __half fsh[];
    __half* Ps = fsh;                    // [128][136] (Q staging, then P)
    __half* Ks = fsh + 128 * 136;        // [128][72]  rows = keys
    __half* Vs = Ks + 128 * 72;          // [64][136]  rows = dims (V^T)
    const uint32_t Pu = smem_u32(Ps);
    const uint32_t Ku = smem_u32(Ks);
    const uint32_t Vu = smem_u32(Vs);

    const int qtb = (QTB - 1) - blockIdx.x;   // big tiles first
    const int h = blockIdx.y, b = blockIdx.z;
    const int kvh = h & (NKV - 1);
    const int bk = b * NKV + kvh;
    const int tid = threadIdx.x;
    const int wid = tid >> 5, lane = tid & 31;
    const int g = lane >> 2, tg = lane & 3;
    const int wrow = wid * 16;
    const int q0 = qtb * 128;

    const int arow  = (lane & 7) + ((lane >> 3) & 1) * 8;
    const int akoff = (lane >> 4) * 8;
    const int brow  = (lane & 7) + ((lane >> 4) & 1) * 8;
    const int bkoff = ((lane >> 3) & 1) * 8;

    // ---- stage Q (pitch 136) ----
    #pragma unroll
    for (int i = 0; i < 4; ++i) {
        int idx = tid + i * 256;
        int row = idx >> 3, seg = idx & 7;
        *(uint4*)&Ps[row * 136 + seg * 8] =
            *(const uint4*)&qh[(size_t)(b * SEQ + q0 + row) * DIMM + h * HD + seg * 8];
    }
    __syncthreads();

    uint32_t qf[4][4];
    #pragma unroll
    for (int ks = 0; ks < 4; ++ks)
        ldsm4(qf[ks], Pu + (uint32_t)((wrow + arow) * 136 + ks * 16 + akoff) * 2u);

    float m_g = -1e30f, m_g8 = -1e30f, l_g = 0.f, l_g8 = 0.f;
    float acc[8][4];
    #pragma unroll
    for (int nt = 0; nt < 8; ++nt)
        #pragma unroll
        for (int v = 0; v < 4; ++v) acc[nt][v] = 0.f;

    // prologue: prefetch tile 0 (K: 128x64, V: 64x128)
    uint4 kr[4], vr[4];
    #pragma unroll
    for (int i = 0; i < 4; ++i) {
        int idx = tid + i * 256;
        { int r = idx >> 3, seg = idx & 7;
          kr[i] = *(const uint4*)&kh[(size_t)(b * SEQ + r) * 512 + kvh * HD + seg * 8]; }
        { int r = idx >> 4, seg = idx & 15;
          vr[i] = *(const uint4*)&vt[((size_t)bk * HD + r) * SEQ + seg * 8]; }
    }

    for (int kt = 0; kt <= qtb; ++kt) {
        __syncthreads();
        #pragma unroll
        for (int i = 0; i < 4; ++i) {
            int idx = tid + i * 256;
            { int r = idx >> 3, seg = idx & 7;
              *(uint4*)&Ks[r * 72 + seg * 8] = kr[i]; }
            { int r = idx >> 4, seg = idx & 15;
              *(uint4*)&Vs[r * 136 + seg * 8] = vr[i]; }
        }
        __syncthreads();

        if (kt < qtb) {
            #pragma unroll
            for (int i = 0; i < 4; ++i) {
                int idx = tid + i * 256;
                { int r = idx >> 3, seg = idx & 7;
                  kr[i] = *(const uint4*)&kh[(size_t)(b * SEQ + (kt + 1) * 128 + r) * 512 + kvh * HD + seg * 8]; }
                { int r = idx >> 4, seg = idx & 15;
                  vr[i] = *(const uint4*)&vt[((size_t)bk * HD + r) * SEQ + (kt + 1) * 128 + seg * 8]; }
            }
        }

        // ---- S = Q @ K^T  (128 keys) ----
        float sA[16][4];
        #pragma unroll
        for (int nt = 0; nt < 16; ++nt)
            #pragma unroll
            for (int v = 0; v < 4; ++v) sA[nt][v] = 0.f;
        #pragma unroll
        for (int ks = 0; ks < 4; ++ks) {
            #pragma unroll
            for (int ntp = 0; ntp < 8; ++ntp) {
                uint32_t t4[4];
                ldsm4(t4, Ku + (uint32_t)((ntp * 16 + brow) * 72 + ks * 16 + bkoff) * 2u);
                mma_f16(sA[2 * ntp],     qf[ks], t4);
                mma_f16(sA[2 * ntp + 1], qf[ks], t4 + 2);
            }
        }
        #pragma unroll
        for (int nt = 0; nt < 16; ++nt) {
            sA[nt][0] *= 0.125f; sA[nt][1] *= 0.125f;
            sA[nt][2] *= 0.125f; sA[nt][3] *= 0.125f;
        }

        // ---- causal mask (diagonal tile only) ----
        if (kt == qtb) {
            const int r1 = wrow + g, r2 = wrow + g + 8;
            #pragma unroll
            for (int nt = 0; nt < 16; ++nt) {
                const int col = nt * 8 + 2 * tg;
                if (col > r1)     sA[nt][0] = -1e30f;
                if (col + 1 > r1) sA[nt][1] = -1e30f;
                if (col > r2)     sA[nt][2] = -1e30f;
                if (col + 1 > r2) sA[nt][3] = -1e30f;
            }
        }

        // ---- online softmax ----
        float mxg = -1e30f, mxg8 = -1e30f;
        #pragma unroll
        for (int nt = 0; nt < 16; ++nt) {
            mxg  = fmaxf(mxg,  fmaxf(sA[nt][0], sA[nt][1]));
            mxg8 = fmaxf(mxg8, fmaxf(sA[nt][2], sA[nt][3]));
        }
        mxg  = fmaxf(mxg,  __shfl_xor_sync(0xffffffffu, mxg, 1));
        mxg  = fmaxf(mxg,  __shfl_xor_sync(0xffffffffu, mxg, 2));
        mxg8 = fmaxf(mxg8, __shfl_xor_sync(0xffffffffu, mxg8, 1));
        mxg8 = fmaxf(mxg8, __shfl_xor_sync(0xffffffffu, mxg8, 2));

        const float mn_g  = fmaxf(m_g,  mxg);
        const float mn_g8 = fmaxf(m_g8, mxg8);
        const float cr_g  = __expf(m_g  - mn_g);
        const float cr_g8 = __expf(m_g8 - mn_g8);

        float sum_g = 0.f, sum_g8 = 0.f;
        #pragma unroll
        for (int nt = 0; nt < 16; ++nt) {
            sA[nt][0] = __expf(sA[nt][0] - mn_g);
            sA[nt][1] = __expf(sA[nt][1] - mn_g);
            sA[nt][2] = __expf(sA[nt][2] - mn_g8);
            sA[nt][3] = __expf(sA[nt][3] - mn_g8);
            sum_g  += sA[nt][0] + sA[nt][1];
            sum_g8 += sA[nt][2] + sA[nt][3];
        }
        sum_g  += __shfl_xor_sync(0xffffffffu, sum_g, 1);
        sum_g  += __shfl_xor_sync(0xffffffffu, sum_g, 2);
        sum_g8 += __shfl_xor_sync(0xffffffffu, sum_g8, 1);
        sum_g8 += __shfl_xor_sync(0xffffffffu, sum_g8, 2);

        m_g = mn_g;  l_g  = l_g  * cr_g  + sum_g;
        m_g8 = mn_g8; l_g8 = l_g8 * cr_g8 + sum_g8;

        // ---- P -> smem (per-warp-private rows, pitch 136) ----
        {
            __half* pr = Ps + (wrow + g) * 136;
            #pragma unroll
            for (int nt = 0; nt < 16; ++nt) {
                *(half2*)(pr + nt * 8 + 2 * tg) = __floats2half2_rn(sA[nt][0], sA[nt][1]);
                *(half2*)(pr + 8 * 136 + nt * 8 + 2 * tg) = __floats2half2_rn(sA[nt][2], sA[nt][3]);
            }
        }
        __syncwarp();

        #pragma unroll
        for (int nt = 0; nt < 8; ++nt) {
            acc[nt][0] *= cr_g;  acc[nt][1] *= cr_g;
            acc[nt][2] *= cr_g8; acc[nt][3] *= cr_g8;
        }

        // ---- O += P @ V  (k = 128 keys -> 8 ks steps) ----
        #pragma unroll
        for (int ks = 0; ks < 8; ++ks) {
            uint32_t af[4];
            ldsm4(af, Pu + (uint32_t)((wrow + arow) * 136 + ks * 16 + akoff) * 2u);
            #pragma unroll
            for (int ntp = 0; ntp < 4; ++ntp) {
                uint32_t t4[4];
                ldsm4(t4, Vu + (uint32_t)((ntp * 16 + brow) * 136 + ks * 16 + bkoff) * 2u);
                mma_f16(acc[2 * ntp],     af, t4);
                mma_f16(acc[2 * ntp + 1], af, t4 + 2);
            }
        }
    }

    // ---- epilogue ----
    const float il_g = 1.f / l_g, il_g8 = 1.f / l_g8;
    __half* ob  = oh + (size_t)(b * SEQ + q0 + wrow + g) * DIMM + h * HD;
    __half* ob8 = ob + 8 * DIMM;
    #pragma unroll
    for (int nt = 0; nt < 8; ++nt) {
        const int col = nt * 8 + 2 * tg;
        *(half2*)(ob + col)  = __floats2half2_rn(acc[nt][0] * il_g,  acc[nt][1] * il_g);
        *(half2*)(ob8 + col) = __floats2half2_rn(acc[nt][2] * il_g8, acc[nt][3] * il_g8);
    }
}

// ============================================================================
extern "C" void kernel_launch(void* const* d_in, const int* in_sizes, int n_in,
                              void* d_out, int out_size)
{
    const float* x   = (const float*)d_in[0];
    const float* Wq  = (const float*)d_in[1];
    const float* Wkv = (const float*)d_in[2];
    const float* Wo  = (const float*)d_in[3];
    const float* cb  = (const float*)d_in[4];
    const float* sb  = (const float*)d_in[5];
    float* out = (float*)d_out;

    __half *xh, *qhp, *khp, *vtp, *ahp, *wqh, *wkvh, *woh;
    cudaGetSymbolAddress((void**)&xh,   g_xh);
    cudaGetSymbolAddress((void**)&qhp,  g_qh);
    cudaGetSymbolAddress((void**)&khp,  g_kh);
    cudaGetSymbolAddress((void**)&vtp,  g_vt);
    cudaGetSymbolAddress((void**)&ahp,  g_ah);
    cudaGetSymbolAddress((void**)&wqh,  g_wqh);
    cudaGetSymbolAddress((void**)&wkvh, g_wkvh);
    cudaGetSymbolAddress((void**)&woh,  g_woh);

    cudaFuncSetAttribute(gemm_h,
                         cudaFuncAttributeMaxDynamicSharedMemorySize, G_SMEM);
    cudaFuncSetAttribute(flash_h,
                         cudaFuncAttributeMaxDynamicSharedMemorySize, FH_SMEM);

    // one-shot fp16 conversion of x + all weights
    {
        int total = CN0 + 2 * CN1 + CN2;
        conv_all<<<(total + 255) / 256, 256>>>(x, Wq, Wkv, Wo, xh, wqh, wkvh, woh);
    }

    // combined Q+KV projection (fused rope / V-transpose epilogues)
    gemm_h<<<dim3(24, NTOK / 128), 128, G_SMEM>>>(
        xh, wqh, wkvh, nullptr, qhp, khp, vtp, cb, sb, NTOK, DIMM, 1);

    // fp16 tensor-core causal GQA flash attention
    flash_h<<<dim3(QTB, NH, BATCH), 256, FH_SMEM>>>(qhp, khp, vtp, ahp);

    // out = att @ Wo (fp32 out)
    gemm_h<<<dim3(16, NTOK / 128), 128, G_SMEM>>>(
        ahp, woh, nullptr, out, nullptr, nullptr, nullptr, nullptr, nullptr,
        NTOK, DIMM, 0);
}

// round 13
// speedup vs baseline: 1.0708x; 1.0002x over previous
#include <cuda_runtime.h>
#include <cuda_fp16.h>
#include <cstdint>

#define SEQ   2048
#define BATCH 2
#define NTOK  (SEQ * BATCH)      // 4096
#define DIMM  2048
#define NH    32
#define NKV   8
#define HD    64
#define KVC   (2 * NKV * HD)     // 1024

// ---- scratch (static device globals: allocation-free) ----
__device__ __half g_xh[(size_t)NTOK * DIMM];
__device__ __half g_qh[(size_t)NTOK * DIMM];            // Q after rope (half)
__device__ __half g_kh[(size_t)NTOK * NKV * HD];        // K after rope (half)
__device__ __half g_vt[(size_t)BATCH * NKV * HD * SEQ]; // V^T [b][kvh][d][n]
__device__ __half g_ah[(size_t)NTOK * DIMM];            // attention out (half)
__device__ __half g_wqh[(size_t)DIMM * DIMM];           // Wq  [K][N] half
__device__ __half g_wkvh[(size_t)DIMM * KVC];           // Wkv [K][N] half
__device__ __half g_woh[(size_t)DIMM * DIMM];           // Wo  [K][N] half

__device__ __forceinline__ uint32_t smem_u32(const void* p) {
    uint32_t a;
    asm("{ .reg .u64 t; cvta.to.shared.u64 t, %1; cvt.u32.u64 %0, t; }" : "=r"(a) : "l"(p));
    return a;
}
__device__ __forceinline__ void mma_f16(float* d, const uint32_t* a, const uint32_t* b) {
    asm volatile(
        "mma.sync.aligned.m16n8k16.row.col.f32.f16.f16.f32 "
        "{%0,%1,%2,%3}, {%4,%5,%6,%7}, {%8,%9}, {%0,%1,%2,%3};"
        : "+f"(d[0]), "+f"(d[1]), "+f"(d[2]), "+f"(d[3])
        : "r"(a[0]), "r"(a[1]), "r"(a[2]), "r"(a[3]), "r"(b[0]), "r"(b[1]));
}
__device__ __forceinline__ void ldsm4(uint32_t* r, uint32_t addr) {
    asm volatile("ldmatrix.sync.aligned.m8n8.x4.shared.b16 {%0,%1,%2,%3}, [%4];"
        : "=r"(r[0]), "=r"(r[1]), "=r"(r[2]), "=r"(r[3]) : "r"(addr));
}
__device__ __forceinline__ void ldsm4t(uint32_t* r, uint32_t addr) {
    asm volatile("ldmatrix.sync.aligned.m8n8.x4.trans.shared.b16 {%0,%1,%2,%3}, [%4];"
        : "=r"(r[0]), "=r"(r[1]), "=r"(r[2]), "=r"(r[3]) : "r"(addr));
}
__device__ __forceinline__ void cp16(uint32_t dst, const void* src) {
    asm volatile("cp.async.cg.shared.global [%0], [%1], 16;" :: "r"(dst), "l"(src));
}
#define CP_COMMIT() asm volatile("cp.async.commit_group;" ::: "memory")

// ============================================================================
// One-shot fp32 -> fp16 convert of x, Wq, Wkv, Wo (8 elems / thread)
// ============================================================================
#define CN0 (NTOK * DIMM / 8)
#define CN1 (DIMM * DIMM / 8)
#define CN2 (DIMM * KVC / 8)
__global__ void conv_all(const float* __restrict__ x, const float* __restrict__ wq,
                         const float* __restrict__ wkv, const float* __restrict__ wo,
                         __half* __restrict__ xh, __half* __restrict__ wqh,
                         __half* __restrict__ wkvh, __half* __restrict__ woh)
{
    int i = blockIdx.x * blockDim.x + threadIdx.x;
    const float* src; __half* dst; int j = i;
    if (j < CN0) { src = x; dst = xh; }
    else {
        j -= CN0;
        if (j < CN1) { src = wq; dst = wqh; }
        else {
            j -= CN1;
            if (j < CN2) { src = wkv; dst = wkvh; }
            else { j -= CN2; if (j >= CN1) return; src = wo; dst = woh; }
        }
    }
    float4 a = ((const float4*)src)[2 * j];
    float4 b = ((const float4*)src)[2 * j + 1];
    half2 h0 = __floats2half2_rn(a.x, a.y), h1 = __floats2half2_rn(a.z, a.w);
    half2 h2 = __floats2half2_rn(b.x, b.y), h3 = __floats2half2_rn(b.z, b.w);
    uint4 r;
    r.x = *(uint32_t*)&h0; r.y = *(uint32_t*)&h1;
    r.z = *(uint32_t*)&h2; r.w = *(uint32_t*)&h3;
    ((uint4*)dst)[j] = r;
}

// ============================================================================
// fp16 mma.sync GEMM: 128 threads (4 warps, 2M x 2N), warp tile 64x64, BK=64,
// 3-stage cp.async, B = W[K][N] via ldmatrix.trans.
// __launch_bounds__(128, 2): cap 250 regs (vs natural 255) -> 2 CTAs/SM.
// mode 0: fp32 out (O-proj).  mode 1: blocks 0-15 Q (rope), 16-23 KV (K/V).
// smem bytes: A 3x18432 @0, B 3x17408 @55296 -> 107520 total.
// ============================================================================
#define G_SMEM 107520

__global__ __launch_bounds__(128, 2) void gemm_h(
    const __half* __restrict__ A,
    const __half* __restrict__ W0, const __half* __restrict__ W1,
    float* __restrict__ Cf, __half* __restrict__ qh,
    __half* __restrict__ kh, __half* __restrict__ vt,
    const float* __restrict__ cb, const float* __restrict__ sb,
    int M, int K, int mode)
{
    extern __shared__ __half hsm[];
    const uint32_t sbase = smem_u32(hsm);
    const int tid = threadIdx.x;
    const int wid = tid >> 5, lane = tid & 31;
    const int g = lane >> 2, tg = lane & 3;
    const int wm = wid & 1, wn = wid >> 1;
    const int nb = blockIdx.x;
    const int m0 = blockIdx.y * 128;

    const __half* W; int Nw, ncol0;
    if (mode == 0 || nb < 16) { W = W0; Nw = DIMM; ncol0 = nb * 128; }
    else                      { W = W1; Nw = KVC;  ncol0 = (nb - 16) * 128; }

    const int arow  = (lane & 7) + ((lane >> 3) & 1) * 8;
    const int akoff = (lane >> 4) * 8;
    const int trow = (lane & 7) + ((lane >> 3) & 1) * 8;
    const int tcol = ((lane >> 4) & 1) * 8;

    const __half* Ab = A + (size_t)m0 * K;

    float acc[4][8][4];
    #pragma unroll
    for (int mt = 0; mt < 4; ++mt)
        #pragma unroll
        for (int nt = 0; nt < 8; ++nt)
            #pragma unroll
            for (int v = 0; v < 4; ++v) acc[mt][nt][v] = 0.f;

    const int NC = K / 64;     // 32

    auto issue_chunk = [&](int s, int k0) {
        const uint32_t abase = sbase + (uint32_t)s * 18432u;
        const uint32_t bbase = sbase + 55296u + (uint32_t)s * 17408u;
        #pragma unroll
        for (int i = 0; i < 8; ++i) {
            const int idx = tid + 128 * i;
            {   // A: [128 m][64 k], pitch 144 B
                const int row = idx >> 3, seg = idx & 7;
                cp16(abase + (uint32_t)(row * 144 + seg * 16),
                     Ab + (size_t)row * K + k0 + seg * 8);
            }
            {   // B: [64 k][128 n], pitch 272 B
                const int row = idx >> 4, seg = idx & 15;
                cp16(bbase + (uint32_t)(row * 272 + seg * 16),
                     W + (size_t)(k0 + row) * Nw + ncol0 + seg * 8);
            }
        }
        CP_COMMIT();
    };

    issue_chunk(0, 0);
    issue_chunk(1, 64);

    for (int c = 0; c < NC; ++c) {
        const int s = c % 3;
        if (c + 2 < NC) {
            issue_chunk((c + 2) % 3, (c + 2) * 64);
            asm volatile("cp.async.wait_group 2;" ::: "memory");
        } else if (c + 1 < NC) {
            asm volatile("cp.async.wait_group 1;" ::: "memory");
        } else {
            asm volatile("cp.async.wait_group 0;" ::: "memory");
        }
        __syncthreads();

        const uint32_t As = sbase + (uint32_t)s * 18432u;
        const uint32_t Bs = sbase + 55296u + (uint32_t)s * 17408u;
        #pragma unroll
        for (int ks = 0; ks < 4; ++ks) {
            uint32_t af[4][4];
            #pragma unroll
            for (int mt = 0; mt < 4; ++mt)
                ldsm4(af[mt], As + (uint32_t)((wm * 64 + mt * 16 + arow) * 72 + ks * 16 + akoff) * 2u);
            #pragma unroll
            for (int ntp = 0; ntp < 4; ++ntp) {
                uint32_t t4[4];
                ldsm4t(t4, Bs + (uint32_t)((ks * 16 + trow) * 136 + wn * 64 + ntp * 16 + tcol) * 2u);
                #pragma unroll
                for (int mt = 0; mt < 4; ++mt) {
                    mma_f16(acc[mt][2 * ntp],     af[mt], t4);
                    mma_f16(acc[mt][2 * ntp + 1], af[mt], t4 + 2);
                }
            }
        }
        __syncthreads();
    }

    // ---- epilogues ----
    if (mode == 0) {
        #pragma unroll
        for (int mt = 0; mt < 4; ++mt) {
            const int row = m0 + wm * 64 + mt * 16 + g;
            #pragma unroll
            for (int nt = 0; nt < 8; ++nt) {
                const int col = ncol0 + wn * 64 + nt * 8 + 2 * tg;
                *(float2*)(Cf + (size_t)row * DIMM + col) =
                    make_float2(acc[mt][nt][0], acc[mt][nt][1]);
                *(float2*)(Cf + (size_t)(row + 8) * DIMM + col) =
                    make_float2(acc[mt][nt][2], acc[mt][nt][3]);
            }
        }
    } else if (nb < 16) {   // Q: rope -> qh
        #pragma unroll
        for (int mt = 0; mt < 4; ++mt) {
            const int row = m0 + wm * 64 + mt * 16 + g;
            const int n1 = row & (SEQ - 1), n2 = (row + 8) & (SEQ - 1);
            #pragma unroll
            for (int nt = 0; nt < 8; ++nt) {
                const int col = ncol0 + wn * 64 + nt * 8 + 2 * tg;
                const int fi = (col & 63) >> 1;
                float c1 = cb[n1 * 32 + fi], s1 = sb[n1 * 32 + fi];
                float c2 = cb[n2 * 32 + fi], s2 = sb[n2 * 32 + fi];
                *(half2*)(qh + (size_t)row * DIMM + col) = __floats2half2_rn(
                    acc[mt][nt][0] * c1 - acc[mt][nt][1] * s1,
                    acc[mt][nt][0] * s1 + acc[mt][nt][1] * c1);
                *(half2*)(qh + (size_t)(row + 8) * DIMM + col) = __floats2half2_rn(
                    acc[mt][nt][2] * c2 - acc[mt][nt][3] * s2,
                    acc[mt][nt][2] * s2 + acc[mt][nt][3] * c2);
            }
        }
    } else {                // KV: K rope -> kh, V transposed scatter -> vt
        #pragma unroll
        for (int mt = 0; mt < 4; ++mt) {
            const int row = m0 + wm * 64 + mt * 16 + g;
            const int n1 = row & (SEQ - 1), n2 = (row + 8) & (SEQ - 1);
            const int b_ = row >> 11;
            #pragma unroll
            for (int nt = 0; nt < 8; ++nt) {
                const int col = ncol0 + wn * 64 + nt * 8 + 2 * tg;
                if (col < 512) {
                    const int fi = (col & 63) >> 1;
                    float c1 = cb[n1 * 32 + fi], s1 = sb[n1 * 32 + fi];
                    float c2 = cb[n2 * 32 + fi], s2 = sb[n2 * 32 + fi];
                    *(half2*)(kh + (size_t)row * 512 + col) = __floats2half2_rn(
                        acc[mt][nt][0] * c1 - acc[mt][nt][1] * s1,
                        acc[mt][nt][0] * s1 + acc[mt][nt][1] * c1);
                    *(half2*)(kh + (size_t)(row + 8) * 512 + col) = __floats2half2_rn(
                        acc[mt][nt][2] * c2 - acc[mt][nt][3] * s2,
                        acc[mt][nt][2] * s2 + acc[mt][nt][3] * c2);
                } else {
                    const int cm = col - 512;
                    const int kvh = cm >> 6, d = cm & 63;
                    __half* vb = vt + ((size_t)((b_ * NKV + kvh) * HD + d)) * SEQ;
                    vb[n1]       = __float2half_rn(acc[mt][nt][0]);
                    vb[SEQ + n1] = __float2half_rn(acc[mt][nt][1]);
                    vb[n2]       = __float2half_rn(acc[mt][nt][2]);
                    vb[SEQ + n2] = __float2half_rn(acc[mt][nt][3]);
                }
            }
        }
    }
}

// ============================================================================
// fp16 flash attention (unchanged from R12 / R8 lineage):
// 128-wide key tiles, register prefetch.
// smem halves: Ps[128][136]@0, Ks[128][72]@17408, Vs[64][136]@26624 (70656 B)
// ============================================================================
#define FH_SMEM 70656
#define QTB     (SEQ / 128)                     // 16

__global__ __launch_bounds__(256) void flash_h(
    const __half* __restrict__ qh, const __half* __restrict__ kh,
    const __half* __restrict__ vt, __half* __restrict__ oh)
{
    extern __shared__ __half fsh[];
    __half* Ps = fsh;                    // [128][136] (Q staging, then P)
    __half* Ks = fsh + 128 * 136;        // [128][72]  rows = keys
    __half* Vs = Ks + 128 * 72;          // [64][136]  rows = dims (V^T)
    const uint32_t Pu = smem_u32(Ps);
    const uint32_t Ku = smem_u32(Ks);
    const uint32_t Vu = smem_u32(Vs);

    const int qtb = (QTB - 1) - blockIdx.x;   // big tiles first
    const int h = blockIdx.y, b = blockIdx.z;
    const int kvh = h & (NKV - 1);
    const int bk = b * NKV + kvh;
    const int tid = threadIdx.x;
    const int wid = tid >> 5, lane = tid & 31;
    const int g = lane >> 2, tg = lane & 3;
    const int wrow = wid * 16;
    const int q0 = qtb * 128;

    const int arow  = (lane & 7) + ((lane >> 3) & 1) * 8;
    const int akoff = (lane >> 4) * 8;
    const int brow  = (lane & 7) + ((lane >> 4) & 1) * 8;
    const int bkoff = ((lane >> 3) & 1) * 8;

    // ---- stage Q (pitch 136) ----
    #pragma unroll
    for (int i = 0; i < 4; ++i) {
        int idx = tid + i * 256;
        int row = idx >> 3, seg = idx & 7;
        *(uint4*)&Ps[row * 136 + seg * 8] =
            *(const uint4*)&qh[(size_t)(b * SEQ + q0 + row) * DIMM + h * HD + seg * 8];
    }
    __syncthreads();

    uint32_t qf[4][4];
    #pragma unroll
    for (int ks = 0; ks < 4; ++ks)
        ldsm4(qf[ks], Pu + (uint32_t)((wrow + arow) * 136 + ks * 16 + akoff) * 2u);

    float m_g = -1e30f, m_g8 = -1e30f, l_g = 0.f, l_g8 = 0.f;
    float acc[8][4];
    #pragma unroll
    for (int nt = 0; nt < 8; ++nt)
        #pragma unroll
        for (int v = 0; v < 4; ++v) acc[nt][v] = 0.f;

    // prologue: prefetch tile 0 (K: 128x64, V: 64x128)
    uint4 kr[4], vr[4];
    #pragma unroll
    for (int i = 0; i < 4; ++i) {
        int idx = tid + i * 256;
        { int r = idx >> 3, seg = idx & 7;
          kr[i] = *(const uint4*)&kh[(size_t)(b * SEQ + r) * 512 + kvh * HD + seg * 8]; }
        { int r = idx >> 4, seg = idx & 15;
          vr[i] = *(const uint4*)&vt[((size_t)bk * HD + r) * SEQ + seg * 8]; }
    }

    for (int kt = 0; kt <= qtb; ++kt) {
        __syncthreads();
        #pragma unroll
        for (int i = 0; i < 4; ++i) {
            int idx = tid + i * 256;
            { int r = idx >> 3, seg = idx & 7;
              *(uint4*)&Ks[r * 72 + seg * 8] = kr[i]; }
            { int r = idx >> 4, seg = idx & 15;
              *(uint4*)&Vs[r * 136 + seg * 8] = vr[i]; }
        }
        __syncthreads();

        if (kt < qtb) {
            #pragma unroll
            for (int i = 0; i < 4; ++i) {
                int idx = tid + i * 256;
                { int r = idx >> 3, seg = idx & 7;
                  kr[i] = *(const uint4*)&kh[(size_t)(b * SEQ + (kt + 1) * 128 + r) * 512 + kvh * HD + seg * 8]; }
                { int r = idx >> 4, seg = idx & 15;
                  vr[i] = *(const uint4*)&vt[((size_t)bk * HD + r) * SEQ + (kt + 1) * 128 + seg * 8]; }
            }
        }

        // ---- S = Q @ K^T  (128 keys) ----
        float sA[16][4];
        #pragma unroll
        for (int nt = 0; nt < 16; ++nt)
            #pragma unroll
            for (int v = 0; v < 4; ++v) sA[nt][v] = 0.f;
        #pragma unroll
        for (int ks = 0; ks < 4; ++ks) {
            #pragma unroll
            for (int ntp = 0; ntp < 8; ++ntp) {
                uint32_t t4[4];
                ldsm4(t4, Ku + (uint32_t)((ntp * 16 + brow) * 72 + ks * 16 + bkoff) * 2u);
                mma_f16(sA[2 * ntp],     qf[ks], t4);
                mma_f16(sA[2 * ntp + 1], qf[ks], t4 + 2);
            }
        }
        #pragma unroll
        for (int nt = 0; nt < 16; ++nt) {
            sA[nt][0] *= 0.125f; sA[nt][1] *= 0.125f;
            sA[nt][2] *= 0.125f; sA[nt][3] *= 0.125f;
        }

        // ---- causal mask (diagonal tile only) ----
        if (kt == qtb) {
            const int r1 = wrow + g, r2 = wrow + g + 8;
            #pragma unroll
            for (int nt = 0; nt < 16; ++nt) {
                const int col = nt * 8 + 2 * tg;
                if (col > r1)     sA[nt][0] = -1e30f;
                if (col + 1 > r1) sA[nt][1] = -1e30f;
                if (col > r2)     sA[nt][2] = -1e30f;
                if (col + 1 > r2) sA[nt][3] = -1e30f;
            }
        }

        // ---- online softmax ----
        float mxg = -1e30f, mxg8 = -1e30f;
        #pragma unroll
        for (int nt = 0; nt < 16; ++nt) {
            mxg  = fmaxf(mxg,  fmaxf(sA[nt][0], sA[nt][1]));
            mxg8 = fmaxf(mxg8, fmaxf(sA[nt][2], sA[nt][3]));
        }
        mxg  = fmaxf(mxg,  __shfl_xor_sync(0xffffffffu, mxg, 1));
        mxg  = fmaxf(mxg,  __shfl_xor_sync(0xffffffffu, mxg, 2));
        mxg8 = fmaxf(mxg8, __shfl_xor_sync(0xffffffffu, mxg8, 1));
        mxg8 = fmaxf(mxg8, __shfl_xor_sync(0xffffffffu, mxg8, 2));

        const float mn_g  = fmaxf(m_g,  mxg);
        const float mn_g8 = fmaxf(m_g8, mxg8);
        const float cr_g  = __expf(m_g  - mn_g);
        const float cr_g8 = __expf(m_g8 - mn_g8);

        float sum_g = 0.f, sum_g8 = 0.f;
        #pragma unroll
        for (int nt = 0; nt < 16; ++nt) {
            sA[nt][0] = __expf(sA[nt][0] - mn_g);
            sA[nt][1] = __expf(sA[nt][1] - mn_g);
            sA[nt][2] = __expf(sA[nt][2] - mn_g8);
            sA[nt][3] = __expf(sA[nt][3] - mn_g8);
            sum_g  += sA[nt][0] + sA[nt][1];
            sum_g8 += sA[nt][2] + sA[nt][3];
        }
        sum_g  += __shfl_xor_sync(0xffffffffu, sum_g, 1);
        sum_g  += __shfl_xor_sync(0xffffffffu, sum_g, 2);
        sum_g8 += __shfl_xor_sync(0xffffffffu, sum_g8, 1);
        sum_g8 += __shfl_xor_sync(0xffffffffu, sum_g8, 2);

        m_g = mn_g;  l_g  = l_g  * cr_g  + sum_g;
        m_g8 = mn_g8; l_g8 = l_g8 * cr_g8 + sum_g8;

        // ---- P -> smem (per-warp-private rows, pitch 136) ----
        {
            __half* pr = Ps + (wrow + g) * 136;
            #pragma unroll
            for (int nt = 0; nt < 16; ++nt) {
                *(half2*)(pr + nt * 8 + 2 * tg) = __floats2half2_rn(sA[nt][0], sA[nt][1]);
                *(half2*)(pr + 8 * 136 + nt * 8 + 2 * tg) = __floats2half2_rn(sA[nt][2], sA[nt][3]);
            }
        }
        __syncwarp();

        #pragma unroll
        for (int nt = 0; nt < 8; ++nt) {
            acc[nt][0] *= cr_g;  acc[nt][1] *= cr_g;
            acc[nt][2] *= cr_g8; acc[nt][3] *= cr_g8;
        }

        // ---- O += P @ V  (k = 128 keys -> 8 ks steps) ----
        #pragma unroll
        for (int ks = 0; ks < 8; ++ks) {
            uint32_t af[4];
            ldsm4(af, Pu + (uint32_t)((wrow + arow) * 136 + ks * 16 + akoff) * 2u);
            #pragma unroll
            for (int ntp = 0; ntp < 4; ++ntp) {
                uint32_t t4[4];
                ldsm4(t4, Vu + (uint32_t)((ntp * 16 + brow) * 136 + ks * 16 + bkoff) * 2u);
                mma_f16(acc[2 * ntp],     af, t4);
                mma_f16(acc[2 * ntp + 1], af, t4 + 2);
            }
        }
    }

    // ---- epilogue ----
    const float il_g = 1.f / l_g, il_g8 = 1.f / l_g8;
    __half* ob  = oh + (size_t)(b * SEQ + q0 + wrow + g) * DIMM + h * HD;
    __half* ob8 = ob + 8 * DIMM;
    #pragma unroll
    for (int nt = 0; nt < 8; ++nt) {
        const int col = nt * 8 + 2 * tg;
        *(half2*)(ob + col)  = __floats2half2_rn(acc[nt][0] * il_g,  acc[nt][1] * il_g);
        *(half2*)(ob8 + col) = __floats2half2_rn(acc[nt][2] * il_g8, acc[nt][3] * il_g8);
    }
}

// ============================================================================
extern "C" void kernel_launch(void* const* d_in, const int* in_sizes, int n_in,
                              void* d_out, int out_size)
{
    const float* x   = (const float*)d_in[0];
    const float* Wq  = (const float*)d_in[1];
    const float* Wkv = (const float*)d_in[2];
    const float* Wo  = (const float*)d_in[3];
    const float* cb  = (const float*)d_in[4];
    const float* sb  = (const float*)d_in[5];
    float* out = (float*)d_out;

    __half *xh, *qhp, *khp, *vtp, *ahp, *wqh, *wkvh, *woh;
    cudaGetSymbolAddress((void**)&xh,   g_xh);
    cudaGetSymbolAddress((void**)&qhp,  g_qh);
    cudaGetSymbolAddress((void**)&khp,  g_kh);
    cudaGetSymbolAddress((void**)&vtp,  g_vt);
    cudaGetSymbolAddress((void**)&ahp,  g_ah);
    cudaGetSymbolAddress((void**)&wqh,  g_wqh);
    cudaGetSymbolAddress((void**)&wkvh, g_wkvh);
    cudaGetSymbolAddress((void**)&woh,  g_woh);

    cudaFuncSetAttribute(gemm_h,
                         cudaFuncAttributeMaxDynamicSharedMemorySize, G_SMEM);
    cudaFuncSetAttribute(flash_h,
                         cudaFuncAttributeMaxDynamicSharedMemorySize, FH_SMEM);

    // one-shot fp16 conversion of x + all weights
    {
        int total = CN0 + 2 * CN1 + CN2;
        conv_all<<<(total + 255) / 256, 256>>>(x, Wq, Wkv, Wo, xh, wqh, wkvh, woh);
    }

    // combined Q+KV projection (fused rope / V-transpose epilogues)
    gemm_h<<<dim3(24, NTOK / 128), 128, G_SMEM>>>(
        xh, wqh, wkvh, nullptr, qhp, khp, vtp, cb, sb, NTOK, DIMM, 1);

    // fp16 tensor-core causal GQA flash attention
    flash_h<<<dim3(QTB, NH, BATCH), 256, FH_SMEM>>>(qhp, khp, vtp, ahp);

    // out = att @ Wo (fp32 out)
    gemm_h<<<dim3(16, NTOK / 128), 128, G_SMEM>>>(
        ahp, woh, nullptr, out, nullptr, nullptr, nullptr, nullptr, nullptr,
        NTOK, DIMM, 0);
}

// round 14
// speedup vs baseline: 1.0926x; 1.0204x over previous
#include <cuda_runtime.h>
#include <cuda_fp16.h>
#include <cstdint>

#define SEQ   2048
#define BATCH 2
#define NTOK  (SEQ * BATCH)      // 4096
#define DIMM  2048
#define NH    32
#define NKV   8
#define HD    64
#define KVC   (2 * NKV * HD)     // 1024

// ---- scratch (static device globals: allocation-free) ----
__device__ __half g_xh[(size_t)NTOK * DIMM];
__device__ __half g_qh[(size_t)NTOK * DIMM];            // Q after rope (half)
__device__ __half g_kh[(size_t)NTOK * NKV * HD];        // K after rope (half)
__device__ __half g_vt[(size_t)BATCH * NKV * HD * SEQ]; // V^T [b][kvh][d][n]
__device__ __half g_ah[(size_t)NTOK * DIMM];            // attention out (half)
__device__ __half g_wqh[(size_t)DIMM * DIMM];           // Wq  [K][N] half
__device__ __half g_wkvh[(size_t)DIMM * KVC];           // Wkv [K][N] half
__device__ __half g_woh[(size_t)DIMM * DIMM];           // Wo  [K][N] half

__device__ __forceinline__ uint32_t smem_u32(const void* p) {
    uint32_t a;
    asm("{ .reg .u64 t; cvta.to.shared.u64 t, %1; cvt.u32.u64 %0, t; }" : "=r"(a) : "l"(p));
    return a;
}
__device__ __forceinline__ void mma_f16(float* d, const uint32_t* a, const uint32_t* b) {
    asm volatile(
        "mma.sync.aligned.m16n8k16.row.col.f32.f16.f16.f32 "
        "{%0,%1,%2,%3}, {%4,%5,%6,%7}, {%8,%9}, {%0,%1,%2,%3};"
        : "+f"(d[0]), "+f"(d[1]), "+f"(d[2]), "+f"(d[3])
        : "r"(a[0]), "r"(a[1]), "r"(a[2]), "r"(a[3]), "r"(b[0]), "r"(b[1]));
}
__device__ __forceinline__ void ldsm4(uint32_t* r, uint32_t addr) {
    asm volatile("ldmatrix.sync.aligned.m8n8.x4.shared.b16 {%0,%1,%2,%3}, [%4];"
        : "=r"(r[0]), "=r"(r[1]), "=r"(r[2]), "=r"(r[3]) : "r"(addr));
}
__device__ __forceinline__ void ldsm4t(uint32_t* r, uint32_t addr) {
    asm volatile("ldmatrix.sync.aligned.m8n8.x4.trans.shared.b16 {%0,%1,%2,%3}, [%4];"
        : "=r"(r[0]), "=r"(r[1]), "=r"(r[2]), "=r"(r[3]) : "r"(addr));
}
__device__ __forceinline__ void cp16(uint32_t dst, const void* src) {
    asm volatile("cp.async.cg.shared.global [%0], [%1], 16;" :: "r"(dst), "l"(src));
}
#define CP_COMMIT() asm volatile("cp.async.commit_group;" ::: "memory")

// ============================================================================
// One-shot fp32 -> fp16 convert of x, Wq, Wkv, Wo (8 elems / thread)
// ============================================================================
#define CN0 (NTOK * DIMM / 8)
#define CN1 (DIMM * DIMM / 8)
#define CN2 (DIMM * KVC / 8)
__global__ void conv_all(const float* __restrict__ x, const float* __restrict__ wq,
                         const float* __restrict__ wkv, const float* __restrict__ wo,
                         __half* __restrict__ xh, __half* __restrict__ wqh,
                         __half* __restrict__ wkvh, __half* __restrict__ woh)
{
    int i = blockIdx.x * blockDim.x + threadIdx.x;
    const float* src; __half* dst; int j = i;
    if (j < CN0) { src = x; dst = xh; }
    else {
        j -= CN0;
        if (j < CN1) { src = wq; dst = wqh; }
        else {
            j -= CN1;
            if (j < CN2) { src = wkv; dst = wkvh; }
            else { j -= CN2; if (j >= CN1) return; src = wo; dst = woh; }
        }
    }
    float4 a = ((const float4*)src)[2 * j];
    float4 b = ((const float4*)src)[2 * j + 1];
    half2 h0 = __floats2half2_rn(a.x, a.y), h1 = __floats2half2_rn(a.z, a.w);
    half2 h2 = __floats2half2_rn(b.x, b.y), h3 = __floats2half2_rn(b.z, b.w);
    uint4 r;
    r.x = *(uint32_t*)&h0; r.y = *(uint32_t*)&h1;
    r.z = *(uint32_t*)&h2; r.w = *(uint32_t*)&h3;
    ((uint4*)dst)[j] = r;
}

// ============================================================================
// fp16 mma.sync GEMM (unchanged; measured 116us / 48% tensor / 2 CTAs/SM)
// ============================================================================
#define G_SMEM 107520

__global__ __launch_bounds__(128, 2) void gemm_h(
    const __half* __restrict__ A,
    const __half* __restrict__ W0, const __half* __restrict__ W1,
    float* __restrict__ Cf, __half* __restrict__ qh,
    __half* __restrict__ kh, __half* __restrict__ vt,
    const float* __restrict__ cb, const float* __restrict__ sb,
    int M, int K, int mode)
{
    extern __shared__ __half hsm[];
    const uint32_t sbase = smem_u32(hsm);
    const int tid = threadIdx.x;
    const int wid = tid >> 5, lane = tid & 31;
    const int g = lane >> 2, tg = lane & 3;
    const int wm = wid & 1, wn = wid >> 1;
    const int nb = blockIdx.x;
    const int m0 = blockIdx.y * 128;

    const __half* W; int Nw, ncol0;
    if (mode == 0 || nb < 16) { W = W0; Nw = DIMM; ncol0 = nb * 128; }
    else                      { W = W1; Nw = KVC;  ncol0 = (nb - 16) * 128; }

    const int arow  = (lane & 7) + ((lane >> 3) & 1) * 8;
    const int akoff = (lane >> 4) * 8;
    const int trow = (lane & 7) + ((lane >> 3) & 1) * 8;
    const int tcol = ((lane >> 4) & 1) * 8;

    const __half* Ab = A + (size_t)m0 * K;

    float acc[4][8][4];
    #pragma unroll
    for (int mt = 0; mt < 4; ++mt)
        #pragma unroll
        for (int nt = 0; nt < 8; ++nt)
            #pragma unroll
            for (int v = 0; v < 4; ++v) acc[mt][nt][v] = 0.f;

    const int NC = K / 64;     // 32

    auto issue_chunk = [&](int s, int k0) {
        const uint32_t abase = sbase + (uint32_t)s * 18432u;
        const uint32_t bbase = sbase + 55296u + (uint32_t)s * 17408u;
        #pragma unroll
        for (int i = 0; i < 8; ++i) {
            const int idx = tid + 128 * i;
            {
                const int row = idx >> 3, seg = idx & 7;
                cp16(abase + (uint32_t)(row * 144 + seg * 16),
                     Ab + (size_t)row * K + k0 + seg * 8);
            }
            {
                const int row = idx >> 4, seg = idx & 15;
                cp16(bbase + (uint32_t)(row * 272 + seg * 16),
                     W + (size_t)(k0 + row) * Nw + ncol0 + seg * 8);
            }
        }
        CP_COMMIT();
    };

    issue_chunk(0, 0);
    issue_chunk(1, 64);

    for (int c = 0; c < NC; ++c) {
        const int s = c % 3;
        if (c + 2 < NC) {
            issue_chunk((c + 2) % 3, (c + 2) * 64);
            asm volatile("cp.async.wait_group 2;" ::: "memory");
        } else if (c + 1 < NC) {
            asm volatile("cp.async.wait_group 1;" ::: "memory");
        } else {
            asm volatile("cp.async.wait_group 0;" ::: "memory");
        }
        __syncthreads();

        const uint32_t As = sbase + (uint32_t)s * 18432u;
        const uint32_t Bs = sbase + 55296u + (uint32_t)s * 17408u;
        #pragma unroll
        for (int ks = 0; ks < 4; ++ks) {
            uint32_t af[4][4];
            #pragma unroll
            for (int mt = 0; mt < 4; ++mt)
                ldsm4(af[mt], As + (uint32_t)((wm * 64 + mt * 16 + arow) * 72 + ks * 16 + akoff) * 2u);
            #pragma unroll
            for (int ntp = 0; ntp < 4; ++ntp) {
                uint32_t t4[4];
                ldsm4t(t4, Bs + (uint32_t)((ks * 16 + trow) * 136 + wn * 64 + ntp * 16 + tcol) * 2u);
                #pragma unroll
                for (int mt = 0; mt < 4; ++mt) {
                    mma_f16(acc[mt][2 * ntp],     af[mt], t4);
                    mma_f16(acc[mt][2 * ntp + 1], af[mt], t4 + 2);
                }
            }
        }
        __syncthreads();
    }

    if (mode == 0) {
        #pragma unroll
        for (int mt = 0; mt < 4; ++mt) {
            const int row = m0 + wm * 64 + mt * 16 + g;
            #pragma unroll
            for (int nt = 0; nt < 8; ++nt) {
                const int col = ncol0 + wn * 64 + nt * 8 + 2 * tg;
                *(float2*)(Cf + (size_t)row * DIMM + col) =
                    make_float2(acc[mt][nt][0], acc[mt][nt][1]);
                *(float2*)(Cf + (size_t)(row + 8) * DIMM + col) =
                    make_float2(acc[mt][nt][2], acc[mt][nt][3]);
            }
        }
    } else if (nb < 16) {   // Q: rope -> qh
        #pragma unroll
        for (int mt = 0; mt < 4; ++mt) {
            const int row = m0 + wm * 64 + mt * 16 + g;
            const int n1 = row & (SEQ - 1), n2 = (row + 8) & (SEQ - 1);
            #pragma unroll
            for (int nt = 0; nt < 8; ++nt) {
                const int col = ncol0 + wn * 64 + nt * 8 + 2 * tg;
                const int fi = (col & 63) >> 1;
                float c1 = cb[n1 * 32 + fi], s1 = sb[n1 * 32 + fi];
                float c2 = cb[n2 * 32 + fi], s2 = sb[n2 * 32 + fi];
                *(half2*)(qh + (size_t)row * DIMM + col) = __floats2half2_rn(
                    acc[mt][nt][0] * c1 - acc[mt][nt][1] * s1,
                    acc[mt][nt][0] * s1 + acc[mt][nt][1] * c1);
                *(half2*)(qh + (size_t)(row + 8) * DIMM + col) = __floats2half2_rn(
                    acc[mt][nt][2] * c2 - acc[mt][nt][3] * s2,
                    acc[mt][nt][2] * s2 + acc[mt][nt][3] * c2);
            }
        }
    } else {                // KV: K rope -> kh, V transposed scatter -> vt
        #pragma unroll
        for (int mt = 0; mt < 4; ++mt) {
            const int row = m0 + wm * 64 + mt * 16 + g;
            const int n1 = row & (SEQ - 1), n2 = (row + 8) & (SEQ - 1);
            const int b_ = row >> 11;
            #pragma unroll
            for (int nt = 0; nt < 8; ++nt) {
                const int col = ncol0 + wn * 64 + nt * 8 + 2 * tg;
                if (col < 512) {
                    const int fi = (col & 63) >> 1;
                    float c1 = cb[n1 * 32 + fi], s1 = sb[n1 * 32 + fi];
                    float c2 = cb[n2 * 32 + fi], s2 = sb[n2 * 32 + fi];
                    *(half2*)(kh + (size_t)row * 512 + col) = __floats2half2_rn(
                        acc[mt][nt][0] * c1 - acc[mt][nt][1] * s1,
                        acc[mt][nt][0] * s1 + acc[mt][nt][1] * c1);
                    *(half2*)(kh + (size_t)(row + 8) * 512 + col) = __floats2half2_rn(
                        acc[mt][nt][2] * c2 - acc[mt][nt][3] * s2,
                        acc[mt][nt][2] * s2 + acc[mt][nt][3] * c2);
                } else {
                    const int cm = col - 512;
                    const int kvh = cm >> 6, d = cm & 63;
                    __half* vb = vt + ((size_t)((b_ * NKV + kvh) * HD + d)) * SEQ;
                    vb[n1]       = __float2half_rn(acc[mt][nt][0]);
                    vb[SEQ + n1] = __float2half_rn(acc[mt][nt][1]);
                    vb[n2]       = __float2half_rn(acc[mt][nt][2]);
                    vb[SEQ + n2] = __float2half_rn(acc[mt][nt][3]);
                }
            }
        }
    }
}

// ============================================================================
// fp16 flash attention v3: 64-key tiles (low regs -> 2 CTAs/SM), 128 q-rows,
// scale folded into Q fragments (exact pow2), register KV prefetch.
// smem halves: Ps[128][72]@0, Ks[64][72]@9216, Vs[64][72]@13824 -> 36864 B.
// ============================================================================
#define FH_SMEM 36864
#define QTB     (SEQ / 128)                     // 16

__global__ __launch_bounds__(256, 2) void flash_h(
    const __half* __restrict__ qh, const __half* __restrict__ kh,
    const __half* __restrict__ vt, __half* __restrict__ oh)
{
    extern __shared__ __half fsh[];
    __half* Ps = fsh;                    // [128][72] (Q staging, then P)
    __half* Ks = fsh + 128 * 72;         // [64][72]  rows = keys
    __half* Vs = Ks + 64 * 72;           // [64][72]  rows = dims (V^T)
    const uint32_t Pu = smem_u32(Ps);
    const uint32_t Ku = smem_u32(Ks);
    const uint32_t Vu = smem_u32(Vs);

    const int qtb = (QTB - 1) - blockIdx.x;   // big tiles first
    const int h = blockIdx.y, b = blockIdx.z;
    const int kvh = h & (NKV - 1);
    const int bk = b * NKV + kvh;
    const int tid = threadIdx.x;
    const int wid = tid >> 5, lane = tid & 31;
    const int g = lane >> 2, tg = lane & 3;
    const int wrow = wid * 16;
    const int q0 = qtb * 128;

    const int arow  = (lane & 7) + ((lane >> 3) & 1) * 8;
    const int akoff = (lane >> 4) * 8;
    const int brow  = (lane & 7) + ((lane >> 4) & 1) * 8;
    const int bkoff = ((lane >> 3) & 1) * 8;

    // ---- stage Q (pitch 72) ----
    #pragma unroll
    for (int i = 0; i < 4; ++i) {
        int idx = tid + i * 256;          // 0..1023
        int row = idx >> 3, seg = idx & 7;
        *(uint4*)&Ps[row * 72 + seg * 8] =
            *(const uint4*)&qh[(size_t)(b * SEQ + q0 + row) * DIMM + h * HD + seg * 8];
    }
    __syncthreads();

    // ---- Q fragments, pre-scaled by 1/8 (exact pow2) ----
    uint32_t qf[4][4];
    {
        const half2 sc = __halves2half2(__float2half_rn(0.125f), __float2half_rn(0.125f));
        #pragma unroll
        for (int ks = 0; ks < 4; ++ks) {
            ldsm4(qf[ks], Pu + (uint32_t)((wrow + arow) * 72 + ks * 16 + akoff) * 2u);
            #pragma unroll
            for (int j = 0; j < 4; ++j) {
                half2 v = *(half2*)&qf[ks][j];
                v = __hmul2(v, sc);
                qf[ks][j] = *(uint32_t*)&v;
            }
        }
    }

    float m_g = -1e30f, m_g8 = -1e30f, l_g = 0.f, l_g8 = 0.f;
    float acc[8][4];
    #pragma unroll
    for (int nt = 0; nt < 8; ++nt)
        #pragma unroll
        for (int v = 0; v < 4; ++v) acc[nt][v] = 0.f;

    const int ktmax = 2 * qtb + 1;

    // prologue: prefetch tile 0 (K: 64x64, V: 64x64)
    uint4 kr[2], vr[2];
    #pragma unroll
    for (int i = 0; i < 2; ++i) {
        int idx = tid + i * 256;          // 0..511
        int r = idx >> 3, seg = idx & 7;
        kr[i] = *(const uint4*)&kh[(size_t)(b * SEQ + r) * 512 + kvh * HD + seg * 8];
        vr[i] = *(const uint4*)&vt[((size_t)bk * HD + r) * SEQ + seg * 8];
    }

    for (int kt = 0; kt <= ktmax; ++kt) {
        __syncthreads();
        #pragma unroll
        for (int i = 0; i < 2; ++i) {
            int idx = tid + i * 256;
            int r = idx >> 3, seg = idx & 7;
            *(uint4*)&Ks[r * 72 + seg * 8] = kr[i];
            *(uint4*)&Vs[r * 72 + seg * 8] = vr[i];
        }
        __syncthreads();

        if (kt < ktmax) {
            #pragma unroll
            for (int i = 0; i < 2; ++i) {
                int idx = tid + i * 256;
                int r = idx >> 3, seg = idx & 7;
                kr[i] = *(const uint4*)&kh[(size_t)(b * SEQ + (kt + 1) * 64 + r) * 512 + kvh * HD + seg * 8];
                vr[i] = *(const uint4*)&vt[((size_t)bk * HD + r) * SEQ + (kt + 1) * 64 + seg * 8];
            }
        }

        // ---- S = Q @ K^T (64 keys) ----
        float sA[8][4];
        #pragma unroll
        for (int nt = 0; nt < 8; ++nt)
            #pragma unroll
            for (int v = 0; v < 4; ++v) sA[nt][v] = 0.f;
        #pragma unroll
        for (int ks = 0; ks < 4; ++ks) {
            #pragma unroll
            for (int ntp = 0; ntp < 4; ++ntp) {
                uint32_t t4[4];
                ldsm4(t4, Ku + (uint32_t)((ntp * 16 + brow) * 72 + ks * 16 + bkoff) * 2u);
                mma_f16(sA[2 * ntp],     qf[ks], t4);
                mma_f16(sA[2 * ntp + 1], qf[ks], t4 + 2);
            }
        }

        // ---- causal mask (last two tiles overlap diagonal) ----
        if (kt >= 2 * qtb) {
            const int qr = q0 + wrow + g;
            const int kc0 = kt * 64;
            #pragma unroll
            for (int nt = 0; nt < 8; ++nt) {
                const int col = kc0 + nt * 8 + 2 * tg;
                if (col > qr)         sA[nt][0] = -1e30f;
                if (col + 1 > qr)     sA[nt][1] = -1e30f;
                if (col > qr + 8)     sA[nt][2] = -1e30f;
                if (col + 1 > qr + 8) sA[nt][3] = -1e30f;
            }
        }

        // ---- online softmax ----
        float mxg = -1e30f, mxg8 = -1e30f;
        #pragma unroll
        for (int nt = 0; nt < 8; ++nt) {
            mxg  = fmaxf(mxg,  fmaxf(sA[nt][0], sA[nt][1]));
            mxg8 = fmaxf(mxg8, fmaxf(sA[nt][2], sA[nt][3]));
        }
        mxg  = fmaxf(mxg,  __shfl_xor_sync(0xffffffffu, mxg, 1));
        mxg  = fmaxf(mxg,  __shfl_xor_sync(0xffffffffu, mxg, 2));
        mxg8 = fmaxf(mxg8, __shfl_xor_sync(0xffffffffu, mxg8, 1));
        mxg8 = fmaxf(mxg8, __shfl_xor_sync(0xffffffffu, mxg8, 2));

        const float mn_g  = fmaxf(m_g,  mxg);
        const float mn_g8 = fmaxf(m_g8, mxg8);
        const float cr_g  = __expf(m_g  - mn_g);
        const float cr_g8 = __expf(m_g8 - mn_g8);

        float sum_g = 0.f, sum_g8 = 0.f;
        #pragma unroll
        for (int nt = 0; nt < 8; ++nt) {
            sA[nt][0] = __expf(sA[nt][0] - mn_g);
            sA[nt][1] = __expf(sA[nt][1] - mn_g);
            sA[nt][2] = __expf(sA[nt][2] - mn_g8);
            sA[nt][3] = __expf(sA[nt][3] - mn_g8);
            sum_g  += sA[nt][0] + sA[nt][1];
            sum_g8 += sA[nt][2] + sA[nt][3];
        }
        sum_g  += __shfl_xor_sync(0xffffffffu, sum_g, 1);
        sum_g  += __shfl_xor_sync(0xffffffffu, sum_g, 2);
        sum_g8 += __shfl_xor_sync(0xffffffffu, sum_g8, 1);
        sum_g8 += __shfl_xor_sync(0xffffffffu, sum_g8, 2);

        m_g = mn_g;  l_g  = l_g  * cr_g  + sum_g;
        m_g8 = mn_g8; l_g8 = l_g8 * cr_g8 + sum_g8;

        // ---- P -> smem (per-warp-private rows, pitch 72) ----
        {
            __half* pr = Ps + (wrow + g) * 72;
            #pragma unroll
            for (int nt = 0; nt < 8; ++nt) {
                *(half2*)(pr + nt * 8 + 2 * tg) = __floats2half2_rn(sA[nt][0], sA[nt][1]);
                *(half2*)(pr + 8 * 72 + nt * 8 + 2 * tg) = __floats2half2_rn(sA[nt][2], sA[nt][3]);
            }
        }
        __syncwarp();

        #pragma unroll
        for (int nt = 0; nt < 8; ++nt) {
            acc[nt][0] *= cr_g;  acc[nt][1] *= cr_g;
            acc[nt][2] *= cr_g8; acc[nt][3] *= cr_g8;
        }

        // ---- O += P @ V (64 keys -> 4 ks steps) ----
        #pragma unroll
        for (int ks = 0; ks < 4; ++ks) {
            uint32_t af[4];
            ldsm4(af, Pu + (uint32_t)((wrow + arow) * 72 + ks * 16 + akoff) * 2u);
            #pragma unroll
            for (int ntp = 0; ntp < 4; ++ntp) {
                uint32_t t4[4];
                ldsm4(t4, Vu + (uint32_t)((ntp * 16 + brow) * 72 + ks * 16 + bkoff) * 2u);
                mma_f16(acc[2 * ntp],     af, t4);
                mma_f16(acc[2 * ntp + 1], af, t4 + 2);
            }
        }
    }

    // ---- epilogue ----
    const float il_g = 1.f / l_g, il_g8 = 1.f / l_g8;
    __half* ob  = oh + (size_t)(b * SEQ + q0 + wrow + g) * DIMM + h * HD;
    __half* ob8 = ob + 8 * DIMM;
    #pragma unroll
    for (int nt = 0; nt < 8; ++nt) {
        const int col = nt * 8 + 2 * tg;
        *(half2*)(ob + col)  = __floats2half2_rn(acc[nt][0] * il_g,  acc[nt][1] * il_g);
        *(half2*)(ob8 + col) = __floats2half2_rn(acc[nt][2] * il_g8, acc[nt][3] * il_g8);
    }
}

// ============================================================================
extern "C" void kernel_launch(void* const* d_in, const int* in_sizes, int n_in,
                              void* d_out, int out_size)
{
    const float* x   = (const float*)d_in[0];
    const float* Wq  = (const float*)d_in[1];
    const float* Wkv = (const float*)d_in[2];
    const float* Wo  = (const float*)d_in[3];
    const float* cb  = (const float*)d_in[4];
    const float* sb  = (const float*)d_in[5];
    float* out = (float*)d_out;

    __half *xh, *qhp, *khp, *vtp, *ahp, *wqh, *wkvh, *woh;
    cudaGetSymbolAddress((void**)&xh,   g_xh);
    cudaGetSymbolAddress((void**)&qhp,  g_qh);
    cudaGetSymbolAddress((void**)&khp,  g_kh);
    cudaGetSymbolAddress((void**)&vtp,  g_vt);
    cudaGetSymbolAddress((void**)&ahp,  g_ah);
    cudaGetSymbolAddress((void**)&wqh,  g_wqh);
    cudaGetSymbolAddress((void**)&wkvh, g_wkvh);
    cudaGetSymbolAddress((void**)&woh,  g_woh);

    cudaFuncSetAttribute(gemm_h,
                         cudaFuncAttributeMaxDynamicSharedMemorySize, G_SMEM);
    cudaFuncSetAttribute(flash_h,
                         cudaFuncAttributeMaxDynamicSharedMemorySize, FH_SMEM);

    // one-shot fp16 conversion of x + all weights
    {
        int total = CN0 + 2 * CN1 + CN2;
        conv_all<<<(total + 255) / 256, 256>>>(x, Wq, Wkv, Wo, xh, wqh, wkvh, woh);
    }

    // combined Q+KV projection (fused rope / V-transpose epilogues)
    gemm_h<<<dim3(24, NTOK / 128), 128, G_SMEM>>>(
        xh, wqh, wkvh, nullptr, qhp, khp, vtp, cb, sb, NTOK, DIMM, 1);

    // fp16 tensor-core causal GQA flash attention (64-key tiles, 2 CTAs/SM)
    flash_h<<<dim3(QTB, NH, BATCH), 256, FH_SMEM>>>(qhp, khp, vtp, ahp);

    // out = att @ Wo (fp32 out)
    gemm_h<<<dim3(16, NTOK / 128), 128, G_SMEM>>>(
        ahp, woh, nullptr, out, nullptr, nullptr, nullptr, nullptr, nullptr,
        NTOK, DIMM, 0);
}

// round 15
// speedup vs baseline: 1.1321x; 1.0362x over previous
#include <cuda_runtime.h>
#include <cuda_fp16.h>
#include <cstdint>

#define SEQ   2048
#define BATCH 2
#define NTOK  (SEQ * BATCH)      // 4096
#define DIMM  2048
#define NH    32
#define NKV   8
#define HD    64
#define KVC   (2 * NKV * HD)     // 1024

// ---- scratch (static device globals: allocation-free) ----
__device__ __half g_xh[(size_t)NTOK * DIMM];
__device__ __half g_qh[(size_t)NTOK * DIMM];            // Q after rope (half)
__device__ __half g_kh[(size_t)NTOK * NKV * HD];        // K after rope (half)
__device__ __half g_vt[(size_t)BATCH * NKV * HD * SEQ]; // V^T [b][kvh][d][n]
__device__ __half g_ah[(size_t)NTOK * DIMM];            // attention out (half)
__device__ __half g_wqh[(size_t)DIMM * DIMM];           // Wq  [K][N] half
__device__ __half g_wkvh[(size_t)DIMM * KVC];           // Wkv [K][N] half
__device__ __half g_woh[(size_t)DIMM * DIMM];           // Wo  [K][N] half

__device__ __forceinline__ uint32_t smem_u32(const void* p) {
    uint32_t a;
    asm("{ .reg .u64 t; cvta.to.shared.u64 t, %1; cvt.u32.u64 %0, t; }" : "=r"(a) : "l"(p));
    return a;
}
__device__ __forceinline__ void mma_f16(float* d, const uint32_t* a, const uint32_t* b) {
    asm volatile(
        "mma.sync.aligned.m16n8k16.row.col.f32.f16.f16.f32 "
        "{%0,%1,%2,%3}, {%4,%5,%6,%7}, {%8,%9}, {%0,%1,%2,%3};"
        : "+f"(d[0]), "+f"(d[1]), "+f"(d[2]), "+f"(d[3])
        : "r"(a[0]), "r"(a[1]), "r"(a[2]), "r"(a[3]), "r"(b[0]), "r"(b[1]));
}
__device__ __forceinline__ void ldsm4(uint32_t* r, uint32_t addr) {
    asm volatile("ldmatrix.sync.aligned.m8n8.x4.shared.b16 {%0,%1,%2,%3}, [%4];"
        : "=r"(r[0]), "=r"(r[1]), "=r"(r[2]), "=r"(r[3]) : "r"(addr));
}
__device__ __forceinline__ void ldsm4t(uint32_t* r, uint32_t addr) {
    asm volatile("ldmatrix.sync.aligned.m8n8.x4.trans.shared.b16 {%0,%1,%2,%3}, [%4];"
        : "=r"(r[0]), "=r"(r[1]), "=r"(r[2]), "=r"(r[3]) : "r"(addr));
}
__device__ __forceinline__ void cp16(uint32_t dst, const void* src) {
    asm volatile("cp.async.cg.shared.global [%0], [%1], 16;" :: "r"(dst), "l"(src));
}
__device__ __forceinline__ uint32_t packh2(float a, float b) {
    half2 h = __floats2half2_rn(a, b);
    return *(uint32_t*)&h;
}
#define CP_COMMIT() asm volatile("cp.async.commit_group;" ::: "memory")

// ============================================================================
// One-shot fp32 -> fp16 convert of x, Wq, Wkv, Wo (8 elems / thread)
// ============================================================================
#define CN0 (NTOK * DIMM / 8)
#define CN1 (DIMM * DIMM / 8)
#define CN2 (DIMM * KVC / 8)
__global__ void conv_all(const float* __restrict__ x, const float* __restrict__ wq,
                         const float* __restrict__ wkv, const float* __restrict__ wo,
                         __half* __restrict__ xh, __half* __restrict__ wqh,
                         __half* __restrict__ wkvh, __half* __restrict__ woh)
{
    int i = blockIdx.x * blockDim.x + threadIdx.x;
    const float* src; __half* dst; int j = i;
    if (j < CN0) { src = x; dst = xh; }
    else {
        j -= CN0;
        if (j < CN1) { src = wq; dst = wqh; }
        else {
            j -= CN1;
            if (j < CN2) { src = wkv; dst = wkvh; }
            else { j -= CN2; if (j >= CN1) return; src = wo; dst = woh; }
        }
    }
    float4 a = ((const float4*)src)[2 * j];
    float4 b = ((const float4*)src)[2 * j + 1];
    half2 h0 = __floats2half2_rn(a.x, a.y), h1 = __floats2half2_rn(a.z, a.w);
    half2 h2 = __floats2half2_rn(b.x, b.y), h3 = __floats2half2_rn(b.z, b.w);
    uint4 r;
    r.x = *(uint32_t*)&h0; r.y = *(uint32_t*)&h1;
    r.z = *(uint32_t*)&h2; r.w = *(uint32_t*)&h3;
    ((uint4*)dst)[j] = r;
}

// ============================================================================
// fp16 mma.sync GEMM (unchanged; measured 116us / 48% tensor / 2 CTAs/SM)
// ============================================================================
#define G_SMEM 107520

__global__ __launch_bounds__(128, 2) void gemm_h(
    const __half* __restrict__ A,
    const __half* __restrict__ W0, const __half* __restrict__ W1,
    float* __restrict__ Cf, __half* __restrict__ qh,
    __half* __restrict__ kh, __half* __restrict__ vt,
    const float* __restrict__ cb, const float* __restrict__ sb,
    int M, int K, int mode)
{
    extern __shared__ __half hsm[];
    const uint32_t sbase = smem_u32(hsm);
    const int tid = threadIdx.x;
    const int wid = tid >> 5, lane = tid & 31;
    const int g = lane >> 2, tg = lane & 3;
    const int wm = wid & 1, wn = wid >> 1;
    const int nb = blockIdx.x;
    const int m0 = blockIdx.y * 128;

    const __half* W; int Nw, ncol0;
    if (mode == 0 || nb < 16) { W = W0; Nw = DIMM; ncol0 = nb * 128; }
    else                      { W = W1; Nw = KVC;  ncol0 = (nb - 16) * 128; }

    const int arow  = (lane & 7) + ((lane >> 3) & 1) * 8;
    const int akoff = (lane >> 4) * 8;
    const int trow = (lane & 7) + ((lane >> 3) & 1) * 8;
    const int tcol = ((lane >> 4) & 1) * 8;

    const __half* Ab = A + (size_t)m0 * K;

    float acc[4][8][4];
    #pragma unroll
    for (int mt = 0; mt < 4; ++mt)
        #pragma unroll
        for (int nt = 0; nt < 8; ++nt)
            #pragma unroll
            for (int v = 0; v < 4; ++v) acc[mt][nt][v] = 0.f;

    const int NC = K / 64;     // 32

    auto issue_chunk = [&](int s, int k0) {
        const uint32_t abase = sbase + (uint32_t)s * 18432u;
        const uint32_t bbase = sbase + 55296u + (uint32_t)s * 17408u;
        #pragma unroll
        for (int i = 0; i < 8; ++i) {
            const int idx = tid + 128 * i;
            {
                const int row = idx >> 3, seg = idx & 7;
                cp16(abase + (uint32_t)(row * 144 + seg * 16),
                     Ab + (size_t)row * K + k0 + seg * 8);
            }
            {
                const int row = idx >> 4, seg = idx & 15;
                cp16(bbase + (uint32_t)(row * 272 + seg * 16),
                     W + (size_t)(k0 + row) * Nw + ncol0 + seg * 8);
            }
        }
        CP_COMMIT();
    };

    issue_chunk(0, 0);
    issue_chunk(1, 64);

    for (int c = 0; c < NC; ++c) {
        const int s = c % 3;
        if (c + 2 < NC) {
            issue_chunk((c + 2) % 3, (c + 2) * 64);
            asm volatile("cp.async.wait_group 2;" ::: "memory");
        } else if (c + 1 < NC) {
            asm volatile("cp.async.wait_group 1;" ::: "memory");
        } else {
            asm volatile("cp.async.wait_group 0;" ::: "memory");
        }
        __syncthreads();

        const uint32_t As = sbase + (uint32_t)s * 18432u;
        const uint32_t Bs = sbase + 55296u + (uint32_t)s * 17408u;
        #pragma unroll
        for (int ks = 0; ks < 4; ++ks) {
            uint32_t af[4][4];
            #pragma unroll
            for (int mt = 0; mt < 4; ++mt)
                ldsm4(af[mt], As + (uint32_t)((wm * 64 + mt * 16 + arow) * 72 + ks * 16 + akoff) * 2u);
            #pragma unroll
            for (int ntp = 0; ntp < 4; ++ntp) {
                uint32_t t4[4];
                ldsm4t(t4, Bs + (uint32_t)((ks * 16 + trow) * 136 + wn * 64 + ntp * 16 + tcol) * 2u);
                #pragma unroll
                for (int mt = 0; mt < 4; ++mt) {
                    mma_f16(acc[mt][2 * ntp],     af[mt], t4);
                    mma_f16(acc[mt][2 * ntp + 1], af[mt], t4 + 2);
                }
            }
        }
        __syncthreads();
    }

    if (mode == 0) {
        #pragma unroll
        for (int mt = 0; mt < 4; ++mt) {
            const int row = m0 + wm * 64 + mt * 16 + g;
            #pragma unroll
            for (int nt = 0; nt < 8; ++nt) {
                const int col = ncol0 + wn * 64 + nt * 8 + 2 * tg;
                *(float2*)(Cf + (size_t)row * DIMM + col) =
                    make_float2(acc[mt][nt][0], acc[mt][nt][1]);
                *(float2*)(Cf + (size_t)(row + 8) * DIMM + col) =
                    make_float2(acc[mt][nt][2], acc[mt][nt][3]);
            }
        }
    } else if (nb < 16) {   // Q: rope -> qh
        #pragma unroll
        for (int mt = 0; mt < 4; ++mt) {
            const int row = m0 + wm * 64 + mt * 16 + g;
            const int n1 = row & (SEQ - 1), n2 = (row + 8) & (SEQ - 1);
            #pragma unroll
            for (int nt = 0; nt < 8; ++nt) {
                const int col = ncol0 + wn * 64 + nt * 8 + 2 * tg;
                const int fi = (col & 63) >> 1;
                float c1 = cb[n1 * 32 + fi], s1 = sb[n1 * 32 + fi];
                float c2 = cb[n2 * 32 + fi], s2 = sb[n2 * 32 + fi];
                *(half2*)(qh + (size_t)row * DIMM + col) = __floats2half2_rn(
                    acc[mt][nt][0] * c1 - acc[mt][nt][1] * s1,
                    acc[mt][nt][0] * s1 + acc[mt][nt][1] * c1);
                *(half2*)(qh + (size_t)(row + 8) * DIMM + col) = __floats2half2_rn(
                    acc[mt][nt][2] * c2 - acc[mt][nt][3] * s2,
                    acc[mt][nt][2] * s2 + acc[mt][nt][3] * c2);
            }
        }
    } else {                // KV: K rope -> kh, V transposed scatter -> vt
        #pragma unroll
        for (int mt = 0; mt < 4; ++mt) {
            const int row = m0 + wm * 64 + mt * 16 + g;
            const int n1 = row & (SEQ - 1), n2 = (row + 8) & (SEQ - 1);
            const int b_ = row >> 11;
            #pragma unroll
            for (int nt = 0; nt < 8; ++nt) {
                const int col = ncol0 + wn * 64 + nt * 8 + 2 * tg;
                if (col < 512) {
                    const int fi = (col & 63) >> 1;
                    float c1 = cb[n1 * 32 + fi], s1 = sb[n1 * 32 + fi];
                    float c2 = cb[n2 * 32 + fi], s2 = sb[n2 * 32 + fi];
                    *(half2*)(kh + (size_t)row * 512 + col) = __floats2half2_rn(
                        acc[mt][nt][0] * c1 - acc[mt][nt][1] * s1,
                        acc[mt][nt][0] * s1 + acc[mt][nt][1] * c1);
                    *(half2*)(kh + (size_t)(row + 8) * 512 + col) = __floats2half2_rn(
                        acc[mt][nt][2] * c2 - acc[mt][nt][3] * s2,
                        acc[mt][nt][2] * s2 + acc[mt][nt][3] * c2);
                } else {
                    const int cm = col - 512;
                    const int kvh = cm >> 6, d = cm & 63;
                    __half* vb = vt + ((size_t)((b_ * NKV + kvh) * HD + d)) * SEQ;
                    vb[n1]       = __float2half_rn(acc[mt][nt][0]);
                    vb[SEQ + n1] = __float2half_rn(acc[mt][nt][1]);
                    vb[n2]       = __float2half_rn(acc[mt][nt][2]);
                    vb[SEQ + n2] = __float2half_rn(acc[mt][nt][3]);
                }
            }
        }
    }
}

// ============================================================================
// fp16 flash attention v4: 64-key tiles, P kept entirely in registers
// (C-fragment of S == A-fragment of PV after half2 packing). No P smem,
// no __syncwarp, no P ldsm. Q staged through the K/V region before mainloop.
// smem: 9216 halves = 18432 B (Ks[64][72]@0, Vs[64][72]@4608; Q stage = both).
// ============================================================================
#define FH_SMEM 18432
#define QTB     (SEQ / 128)                     // 16

__global__ __launch_bounds__(256, 2) void flash_h(
    const __half* __restrict__ qh, const __half* __restrict__ kh,
    const __half* __restrict__ vt, __half* __restrict__ oh)
{
    extern __shared__ __half fsh[];
    __half* Ks = fsh;                    // [64][72] rows = keys
    __half* Vs = fsh + 64 * 72;          // [64][72] rows = dims (V^T)
    const uint32_t Qu = smem_u32(fsh);   // Q staging overlays Ks+Vs
    const uint32_t Ku = smem_u32(Ks);
    const uint32_t Vu = smem_u32(Vs);

    const int qtb = (QTB - 1) - blockIdx.x;   // big tiles first
    const int h = blockIdx.y, b = blockIdx.z;
    const int kvh = h & (NKV - 1);
    const int bk = b * NKV + kvh;
    const int tid = threadIdx.x;
    const int wid = tid >> 5, lane = tid & 31;
    const int g = lane >> 2, tg = lane & 3;
    const int wrow = wid * 16;
    const int q0 = qtb * 128;

    const int arow  = (lane & 7) + ((lane >> 3) & 1) * 8;
    const int akoff = (lane >> 4) * 8;
    const int brow  = (lane & 7) + ((lane >> 4) & 1) * 8;
    const int bkoff = ((lane >> 3) & 1) * 8;

    // ---- stage Q into the (future) K/V region (pitch 72, 128 rows) ----
    #pragma unroll
    for (int i = 0; i < 4; ++i) {
        int idx = tid + i * 256;          // 0..1023
        int row = idx >> 3, seg = idx & 7;
        *(uint4*)&fsh[row * 72 + seg * 8] =
            *(const uint4*)&qh[(size_t)(b * SEQ + q0 + row) * DIMM + h * HD + seg * 8];
    }
    __syncthreads();

    // ---- Q fragments, pre-scaled by 1/8 (exact pow2) ----
    uint32_t qf[4][4];
    {
        const half2 sc = __halves2half2(__float2half_rn(0.125f), __float2half_rn(0.125f));
        #pragma unroll
        for (int ks = 0; ks < 4; ++ks) {
            ldsm4(qf[ks], Qu + (uint32_t)((wrow + arow) * 72 + ks * 16 + akoff) * 2u);
            #pragma unroll
            for (int j = 0; j < 4; ++j) {
                half2 v = *(half2*)&qf[ks][j];
                v = __hmul2(v, sc);
                qf[ks][j] = *(uint32_t*)&v;
            }
        }
    }

    float m_g = -1e30f, m_g8 = -1e30f, l_g = 0.f, l_g8 = 0.f;
    float acc[8][4];
    #pragma unroll
    for (int nt = 0; nt < 8; ++nt)
        #pragma unroll
        for (int v = 0; v < 4; ++v) acc[nt][v] = 0.f;

    const int ktmax = 2 * qtb + 1;

    // prologue: prefetch tile 0 (K: 64x64, V: 64x64)
    uint4 kr[2], vr[2];
    #pragma unroll
    for (int i = 0; i < 2; ++i) {
        int idx = tid + i * 256;          // 0..511
        int r = idx >> 3, seg = idx & 7;
        kr[i] = *(const uint4*)&kh[(size_t)(b * SEQ + r) * 512 + kvh * HD + seg * 8];
        vr[i] = *(const uint4*)&vt[((size_t)bk * HD + r) * SEQ + seg * 8];
    }

    for (int kt = 0; kt <= ktmax; ++kt) {
        __syncthreads();   // all reads of Q-stage / previous K,V done
        #pragma unroll
        for (int i = 0; i < 2; ++i) {
            int idx = tid + i * 256;
            int r = idx >> 3, seg = idx & 7;
            *(uint4*)&Ks[r * 72 + seg * 8] = kr[i];
            *(uint4*)&Vs[r * 72 + seg * 8] = vr[i];
        }
        __syncthreads();

        if (kt < ktmax) {
            #pragma unroll
            for (int i = 0; i < 2; ++i) {
                int idx = tid + i * 256;
                int r = idx >> 3, seg = idx & 7;
                kr[i] = *(const uint4*)&kh[(size_t)(b * SEQ + (kt + 1) * 64 + r) * 512 + kvh * HD + seg * 8];
                vr[i] = *(const uint4*)&vt[((size_t)bk * HD + r) * SEQ + (kt + 1) * 64 + seg * 8];
            }
        }

        // ---- S = Q @ K^T (64 keys) ----
        float sA[8][4];
        #pragma unroll
        for (int nt = 0; nt < 8; ++nt)
            #pragma unroll
            for (int v = 0; v < 4; ++v) sA[nt][v] = 0.f;
        #pragma unroll
        for (int ks = 0; ks < 4; ++ks) {
            #pragma unroll
            for (int ntp = 0; ntp < 4; ++ntp) {
                uint32_t t4[4];
                ldsm4(t4, Ku + (uint32_t)((ntp * 16 + brow) * 72 + ks * 16 + bkoff) * 2u);
                mma_f16(sA[2 * ntp],     qf[ks], t4);
                mma_f16(sA[2 * ntp + 1], qf[ks], t4 + 2);
            }
        }

        // ---- causal mask (last two tiles overlap diagonal) ----
        if (kt >= 2 * qtb) {
            const int qr = q0 + wrow + g;
            const int kc0 = kt * 64;
            #pragma unroll
            for (int nt = 0; nt < 8; ++nt) {
                const int col = kc0 + nt * 8 + 2 * tg;
                if (col > qr)         sA[nt][0] = -1e30f;
                if (col + 1 > qr)     sA[nt][1] = -1e30f;
                if (col > qr + 8)     sA[nt][2] = -1e30f;
                if (col + 1 > qr + 8) sA[nt][3] = -1e30f;
            }
        }

        // ---- online softmax ----
        float mxg = -1e30f, mxg8 = -1e30f;
        #pragma unroll
        for (int nt = 0; nt < 8; ++nt) {
            mxg  = fmaxf(mxg,  fmaxf(sA[nt][0], sA[nt][1]));
            mxg8 = fmaxf(mxg8, fmaxf(sA[nt][2], sA[nt][3]));
        }
        mxg  = fmaxf(mxg,  __shfl_xor_sync(0xffffffffu, mxg, 1));
        mxg  = fmaxf(mxg,  __shfl_xor_sync(0xffffffffu, mxg, 2));
        mxg8 = fmaxf(mxg8, __shfl_xor_sync(0xffffffffu, mxg8, 1));
        mxg8 = fmaxf(mxg8, __shfl_xor_sync(0xffffffffu, mxg8, 2));

        const float mn_g  = fmaxf(m_g,  mxg);
        const float mn_g8 = fmaxf(m_g8, mxg8);
        const float cr_g  = __expf(m_g  - mn_g);
        const float cr_g8 = __expf(m_g8 - mn_g8);

        float sum_g = 0.f, sum_g8 = 0.f;
        #pragma unroll
        for (int nt = 0; nt < 8; ++nt) {
            sA[nt][0] = __expf(sA[nt][0] - mn_g);
            sA[nt][1] = __expf(sA[nt][1] - mn_g);
            sA[nt][2] = __expf(sA[nt][2] - mn_g8);
            sA[nt][3] = __expf(sA[nt][3] - mn_g8);
            sum_g  += sA[nt][0] + sA[nt][1];
            sum_g8 += sA[nt][2] + sA[nt][3];
        }
        sum_g  += __shfl_xor_sync(0xffffffffu, sum_g, 1);
        sum_g  += __shfl_xor_sync(0xffffffffu, sum_g, 2);
        sum_g8 += __shfl_xor_sync(0xffffffffu, sum_g8, 1);
        sum_g8 += __shfl_xor_sync(0xffffffffu, sum_g8, 2);

        m_g = mn_g;  l_g  = l_g  * cr_g  + sum_g;
        m_g8 = mn_g8; l_g8 = l_g8 * cr_g8 + sum_g8;

        // ---- P: convert S C-fragments directly to PV A-fragments (regs) ----
        uint32_t pf[4][4];
        #pragma unroll
        for (int ks = 0; ks < 4; ++ks) {
            pf[ks][0] = packh2(sA[2 * ks][0],     sA[2 * ks][1]);
            pf[ks][1] = packh2(sA[2 * ks][2],     sA[2 * ks][3]);
            pf[ks][2] = packh2(sA[2 * ks + 1][0], sA[2 * ks + 1][1]);
            pf[ks][3] = packh2(sA[2 * ks + 1][2], sA[2 * ks + 1][3]);
        }

        // ---- rescale acc ----
        #pragma unroll
        for (int nt = 0; nt < 8; ++nt) {
            acc[nt][0] *= cr_g;  acc[nt][1] *= cr_g;
            acc[nt][2] *= cr_g8; acc[nt][3] *= cr_g8;
        }

        // ---- O += P @ V (64 keys -> 4 ks steps) ----
        #pragma unroll
        for (int ks = 0; ks < 4; ++ks) {
            #pragma unroll
            for (int ntp = 0; ntp < 4; ++ntp) {
                uint32_t t4[4];
                ldsm4(t4, Vu + (uint32_t)((ntp * 16 + brow) * 72 + ks * 16 + bkoff) * 2u);
                mma_f16(acc[2 * ntp],     pf[ks], t4);
                mma_f16(acc[2 * ntp + 1], pf[ks], t4 + 2);
            }
        }
    }

    // ---- epilogue ----
    const float il_g = 1.f / l_g, il_g8 = 1.f / l_g8;
    __half* ob  = oh + (size_t)(b * SEQ + q0 + wrow + g) * DIMM + h * HD;
    __half* ob8 = ob + 8 * DIMM;
    #pragma unroll
    for (int nt = 0; nt < 8; ++nt) {
        const int col = nt * 8 + 2 * tg;
        *(half2*)(ob + col)  = __floats2half2_rn(acc[nt][0] * il_g,  acc[nt][1] * il_g);
        *(half2*)(ob8 + col) = __floats2half2_rn(acc[nt][2] * il_g8, acc[nt][3] * il_g8);
    }
}

// ============================================================================
extern "C" void kernel_launch(void* const* d_in, const int* in_sizes, int n_in,
                              void* d_out, int out_size)
{
    const float* x   = (const float*)d_in[0];
    const float* Wq  = (const float*)d_in[1];
    const float* Wkv = (const float*)d_in[2];
    const float* Wo  = (const float*)d_in[3];
    const float* cb  = (const float*)d_in[4];
    const float* sb  = (const float*)d_in[5];
    float* out = (float*)d_out;

    __half *xh, *qhp, *khp, *vtp, *ahp, *wqh, *wkvh, *woh;
    cudaGetSymbolAddress((void**)&xh,   g_xh);
    cudaGetSymbolAddress((void**)&qhp,  g_qh);
    cudaGetSymbolAddress((void**)&khp,  g_kh);
    cudaGetSymbolAddress((void**)&vtp,  g_vt);
    cudaGetSymbolAddress((void**)&ahp,  g_ah);
    cudaGetSymbolAddress((void**)&wqh,  g_wqh);
    cudaGetSymbolAddress((void**)&wkvh, g_wkvh);
    cudaGetSymbolAddress((void**)&woh,  g_woh);

    cudaFuncSetAttribute(gemm_h,
                         cudaFuncAttributeMaxDynamicSharedMemorySize, G_SMEM);
    cudaFuncSetAttribute(flash_h,
                         cudaFuncAttributeMaxDynamicSharedMemorySize, FH_SMEM);

    // one-shot fp16 conversion of x + all weights
    {
        int total = CN0 + 2 * CN1 + CN2;
        conv_all<<<(total + 255) / 256, 256>>>(x, Wq, Wkv, Wo, xh, wqh, wkvh, woh);
    }

    // combined Q+KV projection (fused rope / V-transpose epilogues)
    gemm_h<<<dim3(24, NTOK / 128), 128, G_SMEM>>>(
        xh, wqh, wkvh, nullptr, qhp, khp, vtp, cb, sb, NTOK, DIMM, 1);

    // fp16 tensor-core causal GQA flash attention (P in registers)
    flash_h<<<dim3(QTB, NH, BATCH), 256, FH_SMEM>>>(qhp, khp, vtp, ahp);

    // out = att @ Wo (fp32 out)
    gemm_h<<<dim3(16, NTOK / 128), 128, G_SMEM>>>(
        ahp, woh, nullptr, out, nullptr, nullptr, nullptr, nullptr, nullptr,
        NTOK, DIMM, 0);
}

// round 16
// speedup vs baseline: 1.1513x; 1.0169x over previous
#include <cuda_runtime.h>
#include <cuda_fp16.h>
#include <cstdint>

#define SEQ   2048
#define BATCH 2
#define NTOK  (SEQ * BATCH)      // 4096
#define DIMM  2048
#define NH    32
#define NKV   8
#define HD    64
#define KVC   (2 * NKV * HD)     // 1024

// ---- scratch (static device globals: allocation-free) ----
__device__ __half g_xh[(size_t)NTOK * DIMM];
__device__ __half g_qh[(size_t)NTOK * DIMM];            // Q after rope (half)
__device__ __half g_kh[(size_t)NTOK * NKV * HD];        // K after rope (half)
__device__ __half g_vt[(size_t)BATCH * NKV * HD * SEQ]; // V^T [b][kvh][d][n]
__device__ __half g_ah[(size_t)NTOK * DIMM];            // attention out (half)
__device__ __half g_wqh[(size_t)DIMM * DIMM];           // Wq  [K][N] half
__device__ __half g_wkvh[(size_t)DIMM * KVC];           // Wkv [K][N] half
__device__ __half g_woh[(size_t)DIMM * DIMM];           // Wo  [K][N] half

__device__ __forceinline__ uint32_t smem_u32(const void* p) {
    uint32_t a;
    asm("{ .reg .u64 t; cvta.to.shared.u64 t, %1; cvt.u32.u64 %0, t; }" : "=r"(a) : "l"(p));
    return a;
}
__device__ __forceinline__ void mma_f16(float* d, const uint32_t* a, const uint32_t* b) {
    asm volatile(
        "mma.sync.aligned.m16n8k16.row.col.f32.f16.f16.f32 "
        "{%0,%1,%2,%3}, {%4,%5,%6,%7}, {%8,%9}, {%0,%1,%2,%3};"
        : "+f"(d[0]), "+f"(d[1]), "+f"(d[2]), "+f"(d[3])
        : "r"(a[0]), "r"(a[1]), "r"(a[2]), "r"(a[3]), "r"(b[0]), "r"(b[1]));
}
__device__ __forceinline__ void ldsm4(uint32_t* r, uint32_t addr) {
    asm volatile("ldmatrix.sync.aligned.m8n8.x4.shared.b16 {%0,%1,%2,%3}, [%4];"
        : "=r"(r[0]), "=r"(r[1]), "=r"(r[2]), "=r"(r[3]) : "r"(addr));
}
__device__ __forceinline__ void ldsm4t(uint32_t* r, uint32_t addr) {
    asm volatile("ldmatrix.sync.aligned.m8n8.x4.trans.shared.b16 {%0,%1,%2,%3}, [%4];"
        : "=r"(r[0]), "=r"(r[1]), "=r"(r[2]), "=r"(r[3]) : "r"(addr));
}
__device__ __forceinline__ void cp16(uint32_t dst, const void* src) {
    asm volatile("cp.async.cg.shared.global [%0], [%1], 16;" :: "r"(dst), "l"(src));
}
__device__ __forceinline__ uint32_t packh2(float a, float b) {
    half2 h = __floats2half2_rn(a, b);
    return *(uint32_t*)&h;
}
#define CP_COMMIT() asm volatile("cp.async.commit_group;" ::: "memory")

// ============================================================================
// One-shot fp32 -> fp16 convert of x, Wq, Wkv, Wo (8 elems / thread)
// ============================================================================
#define CN0 (NTOK * DIMM / 8)
#define CN1 (DIMM * DIMM / 8)
#define CN2 (DIMM * KVC / 8)
__global__ void conv_all(const float* __restrict__ x, const float* __restrict__ wq,
                         const float* __restrict__ wkv, const float* __restrict__ wo,
                         __half* __restrict__ xh, __half* __restrict__ wqh,
                         __half* __restrict__ wkvh, __half* __restrict__ woh)
{
    int i = blockIdx.x * blockDim.x + threadIdx.x;
    const float* src; __half* dst; int j = i;
    if (j < CN0) { src = x; dst = xh; }
    else {
        j -= CN0;
        if (j < CN1) { src = wq; dst = wqh; }
        else {
            j -= CN1;
            if (j < CN2) { src = wkv; dst = wkvh; }
            else { j -= CN2; if (j >= CN1) return; src = wo; dst = woh; }
        }
    }
    float4 a = ((const float4*)src)[2 * j];
    float4 b = ((const float4*)src)[2 * j + 1];
    half2 h0 = __floats2half2_rn(a.x, a.y), h1 = __floats2half2_rn(a.z, a.w);
    half2 h2 = __floats2half2_rn(b.x, b.y), h3 = __floats2half2_rn(b.z, b.w);
    uint4 r;
    r.x = *(uint32_t*)&h0; r.y = *(uint32_t*)&h1;
    r.z = *(uint32_t*)&h2; r.w = *(uint32_t*)&h3;
    ((uint4*)dst)[j] = r;
}

// ============================================================================
// fp16 mma.sync GEMM, persistent tile loop (grid = 296 = 2 CTAs/SM x 148).
// Inner tile identical to measured-best config: 128 thr, warp 64x64, BK=64,
// 3-stage cp.async, B = W[K][N] via ldmatrix.trans.
// mode 0: fp32 out (O-proj), ntiles=512 (16 nb x 32 m).
// mode 1: ntiles=768 (24 nb x 32 m): nb 0-15 Q (rope), 16-23 KV (K/V).
// ============================================================================
#define G_SMEM 107520
#define G_GRID 296

__global__ __launch_bounds__(128, 2) void gemm_h(
    const __half* __restrict__ A,
    const __half* __restrict__ W0, const __half* __restrict__ W1,
    float* __restrict__ Cf, __half* __restrict__ qh,
    __half* __restrict__ kh, __half* __restrict__ vt,
    const float* __restrict__ cb, const float* __restrict__ sb,
    int K, int ntiles, int nbW, int mode)
{
    extern __shared__ __half hsm[];
    const uint32_t sbase = smem_u32(hsm);
    const int tid = threadIdx.x;
    const int wid = tid >> 5, lane = tid & 31;
    const int g = lane >> 2, tg = lane & 3;
    const int wm = wid & 1, wn = wid >> 1;

    const int arow  = (lane & 7) + ((lane >> 3) & 1) * 8;
    const int akoff = (lane >> 4) * 8;
    const int trow = (lane & 7) + ((lane >> 3) & 1) * 8;
    const int tcol = ((lane >> 4) & 1) * 8;

    for (int t = blockIdx.x; t < ntiles; t += G_GRID) {
        const int nb = t % nbW;
        const int m0 = (t / nbW) * 128;

        const __half* W; int Nw, ncol0;
        if (mode == 0 || nb < 16) { W = W0; Nw = DIMM; ncol0 = nb * 128; }
        else                      { W = W1; Nw = KVC;  ncol0 = (nb - 16) * 128; }

        const __half* Ab = A + (size_t)m0 * K;

        float acc[4][8][4];
        #pragma unroll
        for (int mt = 0; mt < 4; ++mt)
            #pragma unroll
            for (int nt = 0; nt < 8; ++nt)
                #pragma unroll
                for (int v = 0; v < 4; ++v) acc[mt][nt][v] = 0.f;

        const int NC = K / 64;     // 32

        auto issue_chunk = [&](int s, int k0) {
            const uint32_t abase = sbase + (uint32_t)s * 18432u;
            const uint32_t bbase = sbase + 55296u + (uint32_t)s * 17408u;
            #pragma unroll
            for (int i = 0; i < 8; ++i) {
                const int idx = tid + 128 * i;
                {
                    const int row = idx >> 3, seg = idx & 7;
                    cp16(abase + (uint32_t)(row * 144 + seg * 16),
                         Ab + (size_t)row * K + k0 + seg * 8);
                }
                {
                    const int row = idx >> 4, seg = idx & 15;
                    cp16(bbase + (uint32_t)(row * 272 + seg * 16),
                         W + (size_t)(k0 + row) * Nw + ncol0 + seg * 8);
                }
            }
            CP_COMMIT();
        };

        issue_chunk(0, 0);
        issue_chunk(1, 64);

        for (int c = 0; c < NC; ++c) {
            const int s = c % 3;
            if (c + 2 < NC) {
                issue_chunk((c + 2) % 3, (c + 2) * 64);
                asm volatile("cp.async.wait_group 2;" ::: "memory");
            } else if (c + 1 < NC) {
                asm volatile("cp.async.wait_group 1;" ::: "memory");
            } else {
                asm volatile("cp.async.wait_group 0;" ::: "memory");
            }
            __syncthreads();

            const uint32_t As = sbase + (uint32_t)s * 18432u;
            const uint32_t Bs = sbase + 55296u + (uint32_t)s * 17408u;
            #pragma unroll
            for (int ks = 0; ks < 4; ++ks) {
                uint32_t af[4][4];
                #pragma unroll
                for (int mt = 0; mt < 4; ++mt)
                    ldsm4(af[mt], As + (uint32_t)((wm * 64 + mt * 16 + arow) * 72 + ks * 16 + akoff) * 2u);
                #pragma unroll
                for (int ntp = 0; ntp < 4; ++ntp) {
                    uint32_t t4[4];
                    ldsm4t(t4, Bs + (uint32_t)((ks * 16 + trow) * 136 + wn * 64 + ntp * 16 + tcol) * 2u);
                    #pragma unroll
                    for (int mt = 0; mt < 4; ++mt) {
                        mma_f16(acc[mt][2 * ntp],     af[mt], t4);
                        mma_f16(acc[mt][2 * ntp + 1], af[mt], t4 + 2);
                    }
                }
            }
            __syncthreads();
        }

        // ---- epilogues ----
        if (mode == 0) {
            #pragma unroll
            for (int mt = 0; mt < 4; ++mt) {
                const int row = m0 + wm * 64 + mt * 16 + g;
                #pragma unroll
                for (int nt = 0; nt < 8; ++nt) {
                    const int col = ncol0 + wn * 64 + nt * 8 + 2 * tg;
                    *(float2*)(Cf + (size_t)row * DIMM + col) =
                        make_float2(acc[mt][nt][0], acc[mt][nt][1]);
                    *(float2*)(Cf + (size_t)(row + 8) * DIMM + col) =
                        make_float2(acc[mt][nt][2], acc[mt][nt][3]);
                }
            }
        } else if (nb < 16) {   // Q: rope -> qh
            #pragma unroll
            for (int mt = 0; mt < 4; ++mt) {
                const int row = m0 + wm * 64 + mt * 16 + g;
                const int n1 = row & (SEQ - 1), n2 = (row + 8) & (SEQ - 1);
                #pragma unroll
                for (int nt = 0; nt < 8; ++nt) {
                    const int col = ncol0 + wn * 64 + nt * 8 + 2 * tg;
                    const int fi = (col & 63) >> 1;
                    float c1 = cb[n1 * 32 + fi], s1 = sb[n1 * 32 + fi];
                    float c2 = cb[n2 * 32 + fi], s2 = sb[n2 * 32 + fi];
                    *(half2*)(qh + (size_t)row * DIMM + col) = __floats2half2_rn(
                        acc[mt][nt][0] * c1 - acc[mt][nt][1] * s1,
                        acc[mt][nt][0] * s1 + acc[mt][nt][1] * c1);
                    *(half2*)(qh + (size_t)(row + 8) * DIMM + col) = __floats2half2_rn(
                        acc[mt][nt][2] * c2 - acc[mt][nt][3] * s2,
                        acc[mt][nt][2] * s2 + acc[mt][nt][3] * c2);
                }
            }
        } else {                // KV: K rope -> kh, V transposed scatter -> vt
            #pragma unroll
            for (int mt = 0; mt < 4; ++mt) {
                const int row = m0 + wm * 64 + mt * 16 + g;
                const int n1 = row & (SEQ - 1), n2 = (row + 8) & (SEQ - 1);
                const int b_ = row >> 11;
                #pragma unroll
                for (int nt = 0; nt < 8; ++nt) {
                    const int col = ncol0 + wn * 64 + nt * 8 + 2 * tg;
                    if (col < 512) {
                        const int fi = (col & 63) >> 1;
                        float c1 = cb[n1 * 32 + fi], s1 = sb[n1 * 32 + fi];
                        float c2 = cb[n2 * 32 + fi], s2 = sb[n2 * 32 + fi];
                        *(half2*)(kh + (size_t)row * 512 + col) = __floats2half2_rn(
                            acc[mt][nt][0] * c1 - acc[mt][nt][1] * s1,
                            acc[mt][nt][0] * s1 + acc[mt][nt][1] * c1);
                        *(half2*)(kh + (size_t)(row + 8) * 512 + col) = __floats2half2_rn(
                            acc[mt][nt][2] * c2 - acc[mt][nt][3] * s2,
                            acc[mt][nt][2] * s2 + acc[mt][nt][3] * c2);
                    } else {
                        const int cm = col - 512;
                        const int kvh = cm >> 6, d = cm & 63;
                        __half* vb = vt + ((size_t)((b_ * NKV + kvh) * HD + d)) * SEQ;
                        vb[n1]       = __float2half_rn(acc[mt][nt][0]);
                        vb[SEQ + n1] = __float2half_rn(acc[mt][nt][1]);
                        vb[n2]       = __float2half_rn(acc[mt][nt][2]);
                        vb[SEQ + n2] = __float2half_rn(acc[mt][nt][3]);
                    }
                }
            }
        }
        __syncthreads();   // all epilogue reads of smem-independent state done
    }
}

// ============================================================================
// fp16 flash attention v4 (unchanged from R15): 64-key tiles, P in registers.
// smem: 9216 halves = 18432 B.
// ============================================================================
#define FH_SMEM 18432
#define QTB     (SEQ / 128)                     // 16

__global__ __launch_bounds__(256, 2) void flash_h(
    const __half* __restrict__ qh, const __half* __restrict__ kh,
    const __half* __restrict__ vt, __half* __restrict__ oh)
{
    extern __shared__ __half fsh[];
    __half* Ks = fsh;
    __half* Vs = fsh + 64 * 72;
    const uint32_t Qu = smem_u32(fsh);
    const uint32_t Ku = smem_u32(Ks);
    const uint32_t Vu = smem_u32(Vs);

    const int qtb = (QTB - 1) - blockIdx.x;
    const int h = blockIdx.y, b = blockIdx.z;
    const int kvh = h & (NKV - 1);
    const int bk = b * NKV + kvh;
    const int tid = threadIdx.x;
    const int wid = tid >> 5, lane = tid & 31;
    const int g = lane >> 2, tg = lane & 3;
    const int wrow = wid * 16;
    const int q0 = qtb * 128;

    const int arow  = (lane & 7) + ((lane >> 3) & 1) * 8;
    const int akoff = (lane >> 4) * 8;
    const int brow  = (lane & 7) + ((lane >> 4) & 1) * 8;
    const int bkoff = ((lane >> 3) & 1) * 8;

    #pragma unroll
    for (int i = 0; i < 4; ++i) {
        int idx = tid + i * 256;
        int row = idx >> 3, seg = idx & 7;
        *(uint4*)&fsh[row * 72 + seg * 8] =
            *(const uint4*)&qh[(size_t)(b * SEQ + q0 + row) * DIMM + h * HD + seg * 8];
    }
    __syncthreads();

    uint32_t qf[4][4];
    {
        const half2 sc = __halves2half2(__float2half_rn(0.125f), __float2half_rn(0.125f));
        #pragma unroll
        for (int ks = 0; ks < 4; ++ks) {
            ldsm4(qf[ks], Qu + (uint32_t)((wrow + arow) * 72 + ks * 16 + akoff) * 2u);
            #pragma unroll
            for (int j = 0; j < 4; ++j) {
                half2 v = *(half2*)&qf[ks][j];
                v = __hmul2(v, sc);
                qf[ks][j] = *(uint32_t*)&v;
            }
        }
    }

    float m_g = -1e30f, m_g8 = -1e30f, l_g = 0.f, l_g8 = 0.f;
    float acc[8][4];
    #pragma unroll
    for (int nt = 0; nt < 8; ++nt)
        #pragma unroll
        for (int v = 0; v < 4; ++v) acc[nt][v] = 0.f;

    const int ktmax = 2 * qtb + 1;

    uint4 kr[2], vr[2];
    #pragma unroll
    for (int i = 0; i < 2; ++i) {
        int idx = tid + i * 256;
        int r = idx >> 3, seg = idx & 7;
        kr[i] = *(const uint4*)&kh[(size_t)(b * SEQ + r) * 512 + kvh * HD + seg * 8];
        vr[i] = *(const uint4*)&vt[((size_t)bk * HD + r) * SEQ + seg * 8];
    }

    for (int kt = 0; kt <= ktmax; ++kt) {
        __syncthreads();
        #pragma unroll
        for (int i = 0; i < 2; ++i) {
            int idx = tid + i * 256;
            int r = idx >> 3, seg = idx & 7;
            *(uint4*)&Ks[r * 72 + seg * 8] = kr[i];
            *(uint4*)&Vs[r * 72 + seg * 8] = vr[i];
        }
        __syncthreads();

        if (kt < ktmax) {
            #pragma unroll
            for (int i = 0; i < 2; ++i) {
                int idx = tid + i * 256;
                int r = idx >> 3, seg = idx & 7;
                kr[i] = *(const uint4*)&kh[(size_t)(b * SEQ + (kt + 1) * 64 + r) * 512 + kvh * HD + seg * 8];
                vr[i] = *(const uint4*)&vt[((size_t)bk * HD + r) * SEQ + (kt + 1) * 64 + seg * 8];
            }
        }

        float sA[8][4];
        #pragma unroll
        for (int nt = 0; nt < 8; ++nt)
            #pragma unroll
            for (int v = 0; v < 4; ++v) sA[nt][v] = 0.f;
        #pragma unroll
        for (int ks = 0; ks < 4; ++ks) {
            #pragma unroll
            for (int ntp = 0; ntp < 4; ++ntp) {
                uint32_t t4[4];
                ldsm4(t4, Ku + (uint32_t)((ntp * 16 + brow) * 72 + ks * 16 + bkoff) * 2u);
                mma_f16(sA[2 * ntp],     qf[ks], t4);
                mma_f16(sA[2 * ntp + 1], qf[ks], t4 + 2);
            }
        }

        if (kt >= 2 * qtb) {
            const int qr = q0 + wrow + g;
            const int kc0 = kt * 64;
            #pragma unroll
            for (int nt = 0; nt < 8; ++nt) {
                const int col = kc0 + nt * 8 + 2 * tg;
                if (col > qr)         sA[nt][0] = -1e30f;
                if (col + 1 > qr)     sA[nt][1] = -1e30f;
                if (col > qr + 8)     sA[nt][2] = -1e30f;
                if (col + 1 > qr + 8) sA[nt][3] = -1e30f;
            }
        }

        float mxg = -1e30f, mxg8 = -1e30f;
        #pragma unroll
        for (int nt = 0; nt < 8; ++nt) {
            mxg  = fmaxf(mxg,  fmaxf(sA[nt][0], sA[nt][1]));
            mxg8 = fmaxf(mxg8, fmaxf(sA[nt][2], sA[nt][3]));
        }
        mxg  = fmaxf(mxg,  __shfl_xor_sync(0xffffffffu, mxg, 1));
        mxg  = fmaxf(mxg,  __shfl_xor_sync(0xffffffffu, mxg, 2));
        mxg8 = fmaxf(mxg8, __shfl_xor_sync(0xffffffffu, mxg8, 1));
        mxg8 = fmaxf(mxg8, __shfl_xor_sync(0xffffffffu, mxg8, 2));

        const float mn_g  = fmaxf(m_g,  mxg);
        const float mn_g8 = fmaxf(m_g8, mxg8);
        const float cr_g  = __expf(m_g  - mn_g);
        const float cr_g8 = __expf(m_g8 - mn_g8);

        float sum_g = 0.f, sum_g8 = 0.f;
        #pragma unroll
        for (int nt = 0; nt < 8; ++nt) {
            sA[nt][0] = __expf(sA[nt][0] - mn_g);
            sA[nt][1] = __expf(sA[nt][1] - mn_g);
            sA[nt][2] = __expf(sA[nt][2] - mn_g8);
            sA[nt][3] = __expf(sA[nt][3] - mn_g8);
            sum_g  += sA[nt][0] + sA[nt][1];
            sum_g8 += sA[nt][2] + sA[nt][3];
        }
        sum_g  += __shfl_xor_sync(0xffffffffu, sum_g, 1);
        sum_g  += __shfl_xor_sync(0xffffffffu, sum_g, 2);
        sum_g8 += __shfl_xor_sync(0xffffffffu, sum_g8, 1);
        sum_g8 += __shfl_xor_sync(0xffffffffu, sum_g8, 2);

        m_g = mn_g;  l_g  = l_g  * cr_g  + sum_g;
        m_g8 = mn_g8; l_g8 = l_g8 * cr_g8 + sum_g8;

        uint32_t pf[4][4];
        #pragma unroll
        for (int ks = 0; ks < 4; ++ks) {
            pf[ks][0] = packh2(sA[2 * ks][0],     sA[2 * ks][1]);
            pf[ks][1] = packh2(sA[2 * ks][2],     sA[2 * ks][3]);
            pf[ks][2] = packh2(sA[2 * ks + 1][0], sA[2 * ks + 1][1]);
            pf[ks][3] = packh2(sA[2 * ks + 1][2], sA[2 * ks + 1][3]);
        }

        #pragma unroll
        for (int nt = 0; nt < 8; ++nt) {
            acc[nt][0] *= cr_g;  acc[nt][1] *= cr_g;
            acc[nt][2] *= cr_g8; acc[nt][3] *= cr_g8;
        }

        #pragma unroll
        for (int ks = 0; ks < 4; ++ks) {
            #pragma unroll
            for (int ntp = 0; ntp < 4; ++ntp) {
                uint32_t t4[4];
                ldsm4(t4, Vu + (uint32_t)((ntp * 16 + brow) * 72 + ks * 16 + bkoff) * 2u);
                mma_f16(acc[2 * ntp],     pf[ks], t4);
                mma_f16(acc[2 * ntp + 1], pf[ks], t4 + 2);
            }
        }
    }

    const float il_g = 1.f / l_g, il_g8 = 1.f / l_g8;
    __half* ob  = oh + (size_t)(b * SEQ + q0 + wrow + g) * DIMM + h * HD;
    __half* ob8 = ob + 8 * DIMM;
    #pragma unroll
    for (int nt = 0; nt < 8; ++nt) {
        const int col = nt * 8 + 2 * tg;
        *(half2*)(ob + col)  = __floats2half2_rn(acc[nt][0] * il_g,  acc[nt][1] * il_g);
        *(half2*)(ob8 + col) = __floats2half2_rn(acc[nt][2] * il_g8, acc[nt][3] * il_g8);
    }
}

// ============================================================================
extern "C" void kernel_launch(void* const* d_in, const int* in_sizes, int n_in,
                              void* d_out, int out_size)
{
    const float* x   = (const float*)d_in[0];
    const float* Wq  = (const float*)d_in[1];
    const float* Wkv = (const float*)d_in[2];
    const float* Wo  = (const float*)d_in[3];
    const float* cb  = (const float*)d_in[4];
    const float* sb  = (const float*)d_in[5];
    float* out = (float*)d_out;

    __half *xh, *qhp, *khp, *vtp, *ahp, *wqh, *wkvh, *woh;
    cudaGetSymbolAddress((void**)&xh,   g_xh);
    cudaGetSymbolAddress((void**)&qhp,  g_qh);
    cudaGetSymbolAddress((void**)&khp,  g_kh);
    cudaGetSymbolAddress((void**)&vtp,  g_vt);
    cudaGetSymbolAddress((void**)&ahp,  g_ah);
    cudaGetSymbolAddress((void**)&wqh,  g_wqh);
    cudaGetSymbolAddress((void**)&wkvh, g_wkvh);
    cudaGetSymbolAddress((void**)&woh,  g_woh);

    cudaFuncSetAttribute(gemm_h,
                         cudaFuncAttributeMaxDynamicSharedMemorySize, G_SMEM);
    cudaFuncSetAttribute(flash_h,
                         cudaFuncAttributeMaxDynamicSharedMemorySize, FH_SMEM);

    // one-shot fp16 conversion of x + all weights
    {
        int total = CN0 + 2 * CN1 + CN2;
        conv_all<<<(total + 255) / 256, 256>>>(x, Wq, Wkv, Wo, xh, wqh, wkvh, woh);
    }

    // combined Q+KV projection, persistent grid (768 tiles over 296 CTAs)
    gemm_h<<<G_GRID, 128, G_SMEM>>>(
        xh, wqh, wkvh, nullptr, qhp, khp, vtp, cb, sb, DIMM, 768, 24, 1);

    // fp16 tensor-core causal GQA flash attention (P in registers)
    flash_h<<<dim3(QTB, NH, BATCH), 256, FH_SMEM>>>(qhp, khp, vtp, ahp);

    // out = att @ Wo, persistent grid (512 tiles over 296 CTAs)
    gemm_h<<<G_GRID, 128, G_SMEM>>>(
        ahp, woh, nullptr, out, nullptr, nullptr, nullptr, nullptr, nullptr,
        DIMM, 512, 16, 0);
}

// round 17
// speedup vs baseline: 1.1587x; 1.0064x over previous
#include <cuda_runtime.h>
#include <cuda_fp16.h>
#include <cstdint>

#define SEQ   2048
#define BATCH 2
#define NTOK  (SEQ * BATCH)      // 4096
#define DIMM  2048
#define NH    32
#define NKV   8
#define HD    64
#define KVC   (2 * NKV * HD)     // 1024

// ---- scratch (static device globals: allocation-free) ----
__device__ __half g_xh[(size_t)NTOK * DIMM];
__device__ __half g_qh[(size_t)NTOK * DIMM];            // Q after rope (half)
__device__ __half g_kh[(size_t)NTOK * NKV * HD];        // K after rope (half)
__device__ __half g_vt[(size_t)BATCH * NKV * HD * SEQ]; // V^T [b][kvh][d][n]
__device__ __half g_ah[(size_t)NTOK * DIMM];            // attention out (half)
__device__ __half g_wqh[(size_t)DIMM * DIMM];           // Wq  [K][N] half
__device__ __half g_wkvh[(size_t)DIMM * KVC];           // Wkv [K][N] half
__device__ __half g_woh[(size_t)DIMM * DIMM];           // Wo  [K][N] half

__device__ __forceinline__ uint32_t smem_u32(const void* p) {
    uint32_t a;
    asm("{ .reg .u64 t; cvta.to.shared.u64 t, %1; cvt.u32.u64 %0, t; }" : "=r"(a) : "l"(p));
    return a;
}
__device__ __forceinline__ void mma_f16(float* d, const uint32_t* a, const uint32_t* b) {
    asm volatile(
        "mma.sync.aligned.m16n8k16.row.col.f32.f16.f16.f32 "
        "{%0,%1,%2,%3}, {%4,%5,%6,%7}, {%8,%9}, {%0,%1,%2,%3};"
        : "+f"(d[0]), "+f"(d[1]), "+f"(d[2]), "+f"(d[3])
        : "r"(a[0]), "r"(a[1]), "r"(a[2]), "r"(a[3]), "r"(b[0]), "r"(b[1]));
}
__device__ __forceinline__ void ldsm4(uint32_t* r, uint32_t addr) {
    asm volatile("ldmatrix.sync.aligned.m8n8.x4.shared.b16 {%0,%1,%2,%3}, [%4];"
        : "=r"(r[0]), "=r"(r[1]), "=r"(r[2]), "=r"(r[3]) : "r"(addr));
}
__device__ __forceinline__ void ldsm4t(uint32_t* r, uint32_t addr) {
    asm volatile("ldmatrix.sync.aligned.m8n8.x4.trans.shared.b16 {%0,%1,%2,%3}, [%4];"
        : "=r"(r[0]), "=r"(r[1]), "=r"(r[2]), "=r"(r[3]) : "r"(addr));
}
__device__ __forceinline__ void cp16(uint32_t dst, const void* src) {
    asm volatile("cp.async.cg.shared.global [%0], [%1], 16;" :: "r"(dst), "l"(src));
}
__device__ __forceinline__ uint32_t packh2(float a, float b) {
    half2 h = __floats2half2_rn(a, b);
    return *(uint32_t*)&h;
}
#define CP_COMMIT() asm volatile("cp.async.commit_group;" ::: "memory")

// ============================================================================
// One-shot fp32 -> fp16 convert of x, Wq, Wkv, Wo (8 elems / thread)
// ============================================================================
#define CN0 (NTOK * DIMM / 8)
#define CN1 (DIMM * DIMM / 8)
#define CN2 (DIMM * KVC / 8)
__global__ void conv_all(const float* __restrict__ x, const float* __restrict__ wq,
                         const float* __restrict__ wkv, const float* __restrict__ wo,
                         __half* __restrict__ xh, __half* __restrict__ wqh,
                         __half* __restrict__ wkvh, __half* __restrict__ woh)
{
    int i = blockIdx.x * blockDim.x + threadIdx.x;
    const float* src; __half* dst; int j = i;
    if (j < CN0) { src = x; dst = xh; }
    else {
        j -= CN0;
        if (j < CN1) { src = wq; dst = wqh; }
        else {
            j -= CN1;
            if (j < CN2) { src = wkv; dst = wkvh; }
            else { j -= CN2; if (j >= CN1) return; src = wo; dst = woh; }
        }
    }
    float4 a = ((const float4*)src)[2 * j];
    float4 b = ((const float4*)src)[2 * j + 1];
    half2 h0 = __floats2half2_rn(a.x, a.y), h1 = __floats2half2_rn(a.z, a.w);
    half2 h2 = __floats2half2_rn(b.x, b.y), h3 = __floats2half2_rn(b.z, b.w);
    uint4 r;
    r.x = *(uint32_t*)&h0; r.y = *(uint32_t*)&h1;
    r.z = *(uint32_t*)&h2; r.w = *(uint32_t*)&h3;
    ((uint4*)dst)[j] = r;
}

// ============================================================================
// fp16 mma.sync GEMM, persistent tile loop (grid = 296), single barrier per
// K-chunk: wait_group 1 -> syncthreads -> issue chunk c+2 -> compute c.
// (Start-of-iter barrier orders iter-c reads of slot c%3 before any warp's
//  iter-c+1 issue into slot (c+3)%3 == c%3, so the trailing barrier is gone.)
// mode 0: fp32 out (O-proj), ntiles=512.  mode 1: ntiles=768, nb<16 Q / else KV.
// ============================================================================
#define G_SMEM 107520
#define G_GRID 296

__global__ __launch_bounds__(128, 2) void gemm_h(
    const __half* __restrict__ A,
    const __half* __restrict__ W0, const __half* __restrict__ W1,
    float* __restrict__ Cf, __half* __restrict__ qh,
    __half* __restrict__ kh, __half* __restrict__ vt,
    const float* __restrict__ cb, const float* __restrict__ sb,
    int K, int ntiles, int nbW, int mode)
{
    extern __shared__ __half hsm[];
    const uint32_t sbase = smem_u32(hsm);
    const int tid = threadIdx.x;
    const int wid = tid >> 5, lane = tid & 31;
    const int g = lane >> 2, tg = lane & 3;
    const int wm = wid & 1, wn = wid >> 1;

    const int arow  = (lane & 7) + ((lane >> 3) & 1) * 8;
    const int akoff = (lane >> 4) * 8;
    const int trow = (lane & 7) + ((lane >> 3) & 1) * 8;
    const int tcol = ((lane >> 4) & 1) * 8;

    for (int t = blockIdx.x; t < ntiles; t += G_GRID) {
        const int nb = t % nbW;
        const int m0 = (t / nbW) * 128;

        const __half* W; int Nw, ncol0;
        if (mode == 0 || nb < 16) { W = W0; Nw = DIMM; ncol0 = nb * 128; }
        else                      { W = W1; Nw = KVC;  ncol0 = (nb - 16) * 128; }

        const __half* Ab = A + (size_t)m0 * K;

        float acc[4][8][4];
        #pragma unroll
        for (int mt = 0; mt < 4; ++mt)
            #pragma unroll
            for (int nt = 0; nt < 8; ++nt)
                #pragma unroll
                for (int v = 0; v < 4; ++v) acc[mt][nt][v] = 0.f;

        const int NC = K / 64;     // 32

        auto issue_chunk = [&](int s, int k0) {
            const uint32_t abase = sbase + (uint32_t)s * 18432u;
            const uint32_t bbase = sbase + 55296u + (uint32_t)s * 17408u;
            #pragma unroll
            for (int i = 0; i < 8; ++i) {
                const int idx = tid + 128 * i;
                {
                    const int row = idx >> 3, seg = idx & 7;
                    cp16(abase + (uint32_t)(row * 144 + seg * 16),
                         Ab + (size_t)row * K + k0 + seg * 8);
                }
                {
                    const int row = idx >> 4, seg = idx & 15;
                    cp16(bbase + (uint32_t)(row * 272 + seg * 16),
                         W + (size_t)(k0 + row) * Nw + ncol0 + seg * 8);
                }
            }
            CP_COMMIT();
        };

        issue_chunk(0, 0);
        issue_chunk(1, 64);

        for (int c = 0; c < NC; ++c) {
            const int s = c % 3;
            if (c + 1 < NC) {
                asm volatile("cp.async.wait_group 1;" ::: "memory");
            } else {
                asm volatile("cp.async.wait_group 0;" ::: "memory");
            }
            __syncthreads();
            if (c + 2 < NC) issue_chunk((c + 2) % 3, (c + 2) * 64);

            const uint32_t As = sbase + (uint32_t)s * 18432u;
            const uint32_t Bs = sbase + 55296u + (uint32_t)s * 17408u;
            #pragma unroll
            for (int ks = 0; ks < 4; ++ks) {
                uint32_t af[4][4];
                #pragma unroll
                for (int mt = 0; mt < 4; ++mt)
                    ldsm4(af[mt], As + (uint32_t)((wm * 64 + mt * 16 + arow) * 72 + ks * 16 + akoff) * 2u);
                #pragma unroll
                for (int ntp = 0; ntp < 4; ++ntp) {
                    uint32_t t4[4];
                    ldsm4t(t4, Bs + (uint32_t)((ks * 16 + trow) * 136 + wn * 64 + ntp * 16 + tcol) * 2u);
                    #pragma unroll
                    for (int mt = 0; mt < 4; ++mt) {
                        mma_f16(acc[mt][2 * ntp],     af[mt], t4);
                        mma_f16(acc[mt][2 * ntp + 1], af[mt], t4 + 2);
                    }
                }
            }
        }

        // ---- epilogues ----
        if (mode == 0) {
            #pragma unroll
            for (int mt = 0; mt < 4; ++mt) {
                const int row = m0 + wm * 64 + mt * 16 + g;
                #pragma unroll
                for (int nt = 0; nt < 8; ++nt) {
                    const int col = ncol0 + wn * 64 + nt * 8 + 2 * tg;
                    *(float2*)(Cf + (size_t)row * DIMM + col) =
                        make_float2(acc[mt][nt][0], acc[mt][nt][1]);
                    *(float2*)(Cf + (size_t)(row + 8) * DIMM + col) =
                        make_float2(acc[mt][nt][2], acc[mt][nt][3]);
                }
            }
        } else if (nb < 16) {   // Q: rope -> qh
            #pragma unroll
            for (int mt = 0; mt < 4; ++mt) {
                const int row = m0 + wm * 64 + mt * 16 + g;
                const int n1 = row & (SEQ - 1), n2 = (row + 8) & (SEQ - 1);
                #pragma unroll
                for (int nt = 0; nt < 8; ++nt) {
                    const int col = ncol0 + wn * 64 + nt * 8 + 2 * tg;
                    const int fi = (col & 63) >> 1;
                    float c1 = cb[n1 * 32 + fi], s1 = sb[n1 * 32 + fi];
                    float c2 = cb[n2 * 32 + fi], s2 = sb[n2 * 32 + fi];
                    *(half2*)(qh + (size_t)row * DIMM + col) = __floats2half2_rn(
                        acc[mt][nt][0] * c1 - acc[mt][nt][1] * s1,
                        acc[mt][nt][0] * s1 + acc[mt][nt][1] * c1);
                    *(half2*)(qh + (size_t)(row + 8) * DIMM + col) = __floats2half2_rn(
                        acc[mt][nt][2] * c2 - acc[mt][nt][3] * s2,
                        acc[mt][nt][2] * s2 + acc[mt][nt][3] * c2);
                }
            }
        } else {                // KV: K rope -> kh, V transposed scatter -> vt
            #pragma unroll
            for (int mt = 0; mt < 4; ++mt) {
                const int row = m0 + wm * 64 + mt * 16 + g;
                const int n1 = row & (SEQ - 1), n2 = (row + 8) & (SEQ - 1);
                const int b_ = row >> 11;
                #pragma unroll
                for (int nt = 0; nt < 8; ++nt) {
                    const int col = ncol0 + wn * 64 + nt * 8 + 2 * tg;
                    if (col < 512) {
                        const int fi = (col & 63) >> 1;
                        float c1 = cb[n1 * 32 + fi], s1 = sb[n1 * 32 + fi];
                        float c2 = cb[n2 * 32 + fi], s2 = sb[n2 * 32 + fi];
                        *(half2*)(kh + (size_t)row * 512 + col) = __floats2half2_rn(
                            acc[mt][nt][0] * c1 - acc[mt][nt][1] * s1,
                            acc[mt][nt][0] * s1 + acc[mt][nt][1] * c1);
                        *(half2*)(kh + (size_t)(row + 8) * 512 + col) = __floats2half2_rn(
                            acc[mt][nt][2] * c2 - acc[mt][nt][3] * s2,
                            acc[mt][nt][2] * s2 + acc[mt][nt][3] * c2);
                    } else {
                        const int cm = col - 512;
                        const int kvh = cm >> 6, d = cm & 63;
                        __half* vb = vt + ((size_t)((b_ * NKV + kvh) * HD + d)) * SEQ;
                        vb[n1]       = __float2half_rn(acc[mt][nt][0]);
                        vb[SEQ + n1] = __float2half_rn(acc[mt][nt][1]);
                        vb[n2]       = __float2half_rn(acc[mt][nt][2]);
                        vb[SEQ + n2] = __float2half_rn(acc[mt][nt][3]);
                    }
                }
            }
        }
        __syncthreads();   // epilogue done before next tile's prologue issues
    }
}

// ============================================================================
// fp16 flash attention v4 (unchanged from R15/R16): 64-key tiles, P in regs.
// ============================================================================
#define FH_SMEM 18432
#define QTB     (SEQ / 128)                     // 16

__global__ __launch_bounds__(256, 2) void flash_h(
    const __half* __restrict__ qh, const __half* __restrict__ kh,
    const __half* __restrict__ vt, __half* __restrict__ oh)
{
    extern __shared__ __half fsh[];
    __half* Ks = fsh;
    __half* Vs = fsh + 64 * 72;
    const uint32_t Qu = smem_u32(fsh);
    const uint32_t Ku = smem_u32(Ks);
    const uint32_t Vu = smem_u32(Vs);

    const int qtb = (QTB - 1) - blockIdx.x;
    const int h = blockIdx.y, b = blockIdx.z;
    const int kvh = h & (NKV - 1);
    const int bk = b * NKV + kvh;
    const int tid = threadIdx.x;
    const int wid = tid >> 5, lane = tid & 31;
    const int g = lane >> 2, tg = lane & 3;
    const int wrow = wid * 16;
    const int q0 = qtb * 128;

    const int arow  = (lane & 7) + ((lane >> 3) & 1) * 8;
    const int akoff = (lane >> 4) * 8;
    const int brow  = (lane & 7) + ((lane >> 4) & 1) * 8;
    const int bkoff = ((lane >> 3) & 1) * 8;

    #pragma unroll
    for (int i = 0; i < 4; ++i) {
        int idx = tid + i * 256;
        int row = idx >> 3, seg = idx & 7;
        *(uint4*)&fsh[row * 72 + seg * 8] =
            *(const uint4*)&qh[(size_t)(b * SEQ + q0 + row) * DIMM + h * HD + seg * 8];
    }
    __syncthreads();

    uint32_t qf[4][4];
    {
        const half2 sc = __halves2half2(__float2half_rn(0.125f), __float2half_rn(0.125f));
        #pragma unroll
        for (int ks = 0; ks < 4; ++ks) {
            ldsm4(qf[ks], Qu + (uint32_t)((wrow + arow) * 72 + ks * 16 + akoff) * 2u);
            #pragma unroll
            for (int j = 0; j < 4; ++j) {
                half2 v = *(half2*)&qf[ks][j];
                v = __hmul2(v, sc);
                qf[ks][j] = *(uint32_t*)&v;
            }
        }
    }

    float m_g = -1e30f, m_g8 = -1e30f, l_g = 0.f, l_g8 = 0.f;
    float acc[8][4];
    #pragma unroll
    for (int nt = 0; nt < 8; ++nt)
        #pragma unroll
        for (int v = 0; v < 4; ++v) acc[nt][v] = 0.f;

    const int ktmax = 2 * qtb + 1;

    uint4 kr[2], vr[2];
    #pragma unroll
    for (int i = 0; i < 2; ++i) {
        int idx = tid + i * 256;
        int r = idx >> 3, seg = idx & 7;
        kr[i] = *(const uint4*)&kh[(size_t)(b * SEQ + r) * 512 + kvh * HD + seg * 8];
        vr[i] = *(const uint4*)&vt[((size_t)bk * HD + r) * SEQ + seg * 8];
    }

    for (int kt = 0; kt <= ktmax; ++kt) {
        __syncthreads();
        #pragma unroll
        for (int i = 0; i < 2; ++i) {
            int idx = tid + i * 256;
            int r = idx >> 3, seg = idx & 7;
            *(uint4*)&Ks[r * 72 + seg * 8] = kr[i];
            *(uint4*)&Vs[r * 72 + seg * 8] = vr[i];
        }
        __syncthreads();

        if (kt < ktmax) {
            #pragma unroll
            for (int i = 0; i < 2; ++i) {
                int idx = tid + i * 256;
                int r = idx >> 3, seg = idx & 7;
                kr[i] = *(const uint4*)&kh[(size_t)(b * SEQ + (kt + 1) * 64 + r) * 512 + kvh * HD + seg * 8];
                vr[i] = *(const uint4*)&vt[((size_t)bk * HD + r) * SEQ + (kt + 1) * 64 + seg * 8];
            }
        }

        float sA[8][4];
        #pragma unroll
        for (int nt = 0; nt < 8; ++nt)
            #pragma unroll
            for (int v = 0; v < 4; ++v) sA[nt][v] = 0.f;
        #pragma unroll
        for (int ks = 0; ks < 4; ++ks) {
            #pragma unroll
            for (int ntp = 0; ntp < 4; ++ntp) {
                uint32_t t4[4];
                ldsm4(t4, Ku + (uint32_t)((ntp * 16 + brow) * 72 + ks * 16 + bkoff) * 2u);
                mma_f16(sA[2 * ntp],     qf[ks], t4);
                mma_f16(sA[2 * ntp + 1], qf[ks], t4 + 2);
            }
        }

        if (kt >= 2 * qtb) {
            const int qr = q0 + wrow + g;
            const int kc0 = kt * 64;
            #pragma unroll
            for (int nt = 0; nt < 8; ++nt) {
                const int col = kc0 + nt * 8 + 2 * tg;
                if (col > qr)         sA[nt][0] = -1e30f;
                if (col + 1 > qr)     sA[nt][1] = -1e30f;
                if (col > qr + 8)     sA[nt][2] = -1e30f;
                if (col + 1 > qr + 8) sA[nt][3] = -1e30f;
            }
        }

        float mxg = -1e30f, mxg8 = -1e30f;
        #pragma unroll
        for (int nt = 0; nt < 8; ++nt) {
            mxg  = fmaxf(mxg,  fmaxf(sA[nt][0], sA[nt][1]));
            mxg8 = fmaxf(mxg8, fmaxf(sA[nt][2], sA[nt][3]));
        }
        mxg  = fmaxf(mxg,  __shfl_xor_sync(0xffffffffu, mxg, 1));
        mxg  = fmaxf(mxg,  __shfl_xor_sync(0xffffffffu, mxg, 2));
        mxg8 = fmaxf(mxg8, __shfl_xor_sync(0xffffffffu, mxg8, 1));
        mxg8 = fmaxf(mxg8, __shfl_xor_sync(0xffffffffu, mxg8, 2));

        const float mn_g  = fmaxf(m_g,  mxg);
        const float mn_g8 = fmaxf(m_g8, mxg8);
        const float cr_g  = __expf(m_g  - mn_g);
        const float cr_g8 = __expf(m_g8 - mn_g8);

        float sum_g = 0.f, sum_g8 = 0.f;
        #pragma unroll
        for (int nt = 0; nt < 8; ++nt) {
            sA[nt][0] = __expf(sA[nt][0] - mn_g);
            sA[nt][1] = __expf(sA[nt][1] - mn_g);
            sA[nt][2] = __expf(sA[nt][2] - mn_g8);
            sA[nt][3] = __expf(sA[nt][3] - mn_g8);
            sum_g  += sA[nt][0] + sA[nt][1];
            sum_g8 += sA[nt][2] + sA[nt][3];
        }
        sum_g  += __shfl_xor_sync(0xffffffffu, sum_g, 1);
        sum_g  += __shfl_xor_sync(0xffffffffu, sum_g, 2);
        sum_g8 += __shfl_xor_sync(0xffffffffu, sum_g8, 1);
        sum_g8 += __shfl_xor_sync(0xffffffffu, sum_g8, 2);

        m_g = mn_g;  l_g  = l_g  * cr_g  + sum_g;
        m_g8 = mn_g8; l_g8 = l_g8 * cr_g8 + sum_g8;

        uint32_t pf[4][4];
        #pragma unroll
        for (int ks = 0; ks < 4; ++ks) {
            pf[ks][0] = packh2(sA[2 * ks][0],     sA[2 * ks][1]);
            pf[ks][1] = packh2(sA[2 * ks][2],     sA[2 * ks][3]);
            pf[ks][2] = packh2(sA[2 * ks + 1][0], sA[2 * ks + 1][1]);
            pf[ks][3] = packh2(sA[2 * ks + 1][2], sA[2 * ks + 1][3]);
        }

        #pragma unroll
        for (int nt = 0; nt < 8; ++nt) {
            acc[nt][0] *= cr_g;  acc[nt][1] *= cr_g;
            acc[nt][2] *= cr_g8; acc[nt][3] *= cr_g8;
        }

        #pragma unroll
        for (int ks = 0; ks < 4; ++ks) {
            #pragma unroll
            for (int ntp = 0; ntp < 4; ++ntp) {
                uint32_t t4[4];
                ldsm4(t4, Vu + (uint32_t)((ntp * 16 + brow) * 72 + ks * 16 + bkoff) * 2u);
                mma_f16(acc[2 * ntp],     pf[ks], t4);
                mma_f16(acc[2 * ntp + 1], pf[ks], t4 + 2);
            }
        }
    }

    const float il_g = 1.f / l_g, il_g8 = 1.f / l_g8;
    __half* ob  = oh + (size_t)(b * SEQ + q0 + wrow + g) * DIMM + h * HD;
    __half* ob8 = ob + 8 * DIMM;
    #pragma unroll
    for (int nt = 0; nt < 8; ++nt) {
        const int col = nt * 8 + 2 * tg;
        *(half2*)(ob + col)  = __floats2half2_rn(acc[nt][0] * il_g,  acc[nt][1] * il_g);
        *(half2*)(ob8 + col) = __floats2half2_rn(acc[nt][2] * il_g8, acc[nt][3] * il_g8);
    }
}

// ============================================================================
extern "C" void kernel_launch(void* const* d_in, const int* in_sizes, int n_in,
                              void* d_out, int out_size)
{
    const float* x   = (const float*)d_in[0];
    const float* Wq  = (const float*)d_in[1];
    const float* Wkv = (const float*)d_in[2];
    const float* Wo  = (const float*)d_in[3];
    const float* cb  = (const float*)d_in[4];
    const float* sb  = (const float*)d_in[5];
    float* out = (float*)d_out;

    __half *xh, *qhp, *khp, *vtp, *ahp, *wqh, *wkvh, *woh;
    cudaGetSymbolAddress((void**)&xh,   g_xh);
    cudaGetSymbolAddress((void**)&qhp,  g_qh);
    cudaGetSymbolAddress((void**)&khp,  g_kh);
    cudaGetSymbolAddress((void**)&vtp,  g_vt);
    cudaGetSymbolAddress((void**)&ahp,  g_ah);
    cudaGetSymbolAddress((void**)&wqh,  g_wqh);
    cudaGetSymbolAddress((void**)&wkvh, g_wkvh);
    cudaGetSymbolAddress((void**)&woh,  g_woh);

    cudaFuncSetAttribute(gemm_h,
                         cudaFuncAttributeMaxDynamicSharedMemorySize, G_SMEM);
    cudaFuncSetAttribute(flash_h,
                         cudaFuncAttributeMaxDynamicSharedMemorySize, FH_SMEM);

    // one-shot fp16 conversion of x + all weights
    {
        int total = CN0 + 2 * CN1 + CN2;
        conv_all<<<(total + 255) / 256, 256>>>(x, Wq, Wkv, Wo, xh, wqh, wkvh, woh);
    }

    // combined Q+KV projection, persistent grid (768 tiles over 296 CTAs)
    gemm_h<<<G_GRID, 128, G_SMEM>>>(
        xh, wqh, wkvh, nullptr, qhp, khp, vtp, cb, sb, DIMM, 768, 24, 1);

    // fp16 tensor-core causal GQA flash attention (P in registers)
    flash_h<<<dim3(QTB, NH, BATCH), 256, FH_SMEM>>>(qhp, khp, vtp, ahp);

    // out = att @ Wo, persistent grid (512 tiles over 296 CTAs)
    gemm_h<<<G_GRID, 128, G_SMEM>>>(
        ahp, woh, nullptr, out, nullptr, nullptr, nullptr, nullptr, nullptr,
        DIMM, 512, 16, 0);
}